// round 8
// baseline (speedup 1.0000x reference)
#include <cuda_runtime.h>

// Problem constants (fixed shapes from the reference)
constexpr int Bn = 4;       // batch
constexpr int Nn = 16384;   // points per cloud
constexpr int Pn = 1024;    // npoint (FPS samples)
constexpr int Sn = 64;      // nsample (ball query)

// Scratch: ball query indices (B,P,S). 1 MB.
__device__ int g_ball_idx[Bn * Pn * Sn];

// ---- packed f32x2 helpers (sm_100+). Per-lane semantics identical to
// __fadd_rn / __fmul_rn, so FPS distances stay bit-exact vs the scalar path.
typedef unsigned long long ull;
__device__ __forceinline__ ull pk2(float lo, float hi) {
    ull r; asm("mov.b64 %0,{%1,%2};" : "=l"(r) : "f"(lo), "f"(hi)); return r;
}
__device__ __forceinline__ void upk2(ull v, float& lo, float& hi) {
    asm("mov.b64 {%0,%1},%2;" : "=f"(lo), "=f"(hi) : "l"(v));
}
__device__ __forceinline__ ull addx2(ull a, ull b) {
    ull r; asm("add.rn.f32x2 %0,%1,%2;" : "=l"(r) : "l"(a), "l"(b)); return r;
}
__device__ __forceinline__ ull mulx2(ull a, ull b) {
    ull r; asm("mul.rn.f32x2 %0,%1,%2;" : "=l"(r) : "l"(a), "l"(b)); return r;
}

__device__ __forceinline__ unsigned mapa_sh(unsigned addr, int rank) {
    unsigned r;
    asm("mapa.shared::cluster.u32 %0, %1, %2;" : "=r"(r) : "r"(addr), "r"(rank));
    return r;
}
__device__ __forceinline__ void mbar_wait_acq(unsigned addr, unsigned parity) {
    unsigned done;
    asm volatile(
        "{\n\t.reg .pred p;\n\t"
        "mbarrier.try_wait.parity.acquire.cluster.shared::cta.b64 p, [%1], %2;\n\t"
        "selp.b32 %0, 1, 0, p;\n\t}"
        : "=r"(done) : "r"(addr), "r"(parity) : "memory");
    while (!done) {
        asm volatile(
            "{\n\t.reg .pred p;\n\t"
            "mbarrier.try_wait.parity.acquire.cluster.shared::cta.b64 p, [%1], %2, 0x989680;\n\t"
            "selp.b32 %0, 1, 0, p;\n\t}"
            : "=r"(done) : "r"(addr), "r"(parity) : "memory");
    }
}

// ---------------------------------------------------------------------------
// Kernel 1: Furthest Point Sampling — 4-CTA cluster per batch.
// Each CTA (512 threads) owns 4096 points fully in registers (packed f32x2);
// full-cloud coord copy in smem for the per-iter broadcast. Per-iter argmax:
//   per-warp redux.max on dist bits (d^2>=0 -> bit order == float order),
//   redux.min on candidate global index (-> jnp.argmax first-match tiebreak),
//   lane0 atomicMax of packed (dist<<32 | ~idx) into a smem key,
//   ONE __syncthreads, tid0 DSMEM-stores the key to all 4 mailboxes +
//   mbarrier.arrive.release.cluster, everyone acquire-waits (parity/iter),
//   local max over the 4 keys. Double-buffered key+mailboxes.
// No barrier.cluster / no L1 flush in the loop.
// ---------------------------------------------------------------------------
constexpr int FPS_CL   = 4;                 // CTAs per batch (cluster size)
constexpr int FPS_PART = Nn / FPS_CL;       // 4096 points per CTA
constexpr int FPS_NT   = 512;               // threads per CTA
constexpr int FPS_PPT  = FPS_PART / FPS_NT; // 8 points per thread
constexpr int FPS_NPAIR = FPS_PPT / 2;      // 4 packed pairs per thread
// smem floats: sxy[2*Nn] + szf[Nn], then ull aux[11]:
//   aux[0..1]=s_key[2], aux[2..9]=mbox[2][4], aux[10]=mbarrier
constexpr int FPS_SMEM = 3 * Nn * 4 + 11 * 8;

__global__ __launch_bounds__(FPS_NT, 1) __cluster_dims__(FPS_CL, 1, 1)
void fps_kernel(const float* __restrict__ xyz, float* __restrict__ new_xyz)
{
    const int b = blockIdx.x / FPS_CL;
    const int r = blockIdx.x % FPS_CL;     // cluster rank
    const float* pts = xyz + (size_t)b * Nn * 3;

    extern __shared__ float sm[];
    float2* sxy  = reinterpret_cast<float2*>(sm);   // [Nn]
    float*  szf  = sm + 2 * Nn;                     // [Nn]
    ull*    aux  = reinterpret_cast<ull*>(sm + 3 * Nn);
    ull*    skey = aux;                             // [2]
    ull*    mbox = aux + 2;                         // [2][FPS_CL]
    ull*    mbar = aux + 10;

    const int tid  = threadIdx.x;
    const int lane = tid & 31;

    // Stage the full cloud into this CTA's smem (for broadcasts).
    for (int p = tid; p < Nn; p += FPS_NT) {
        float x = pts[p * 3 + 0];
        float y = pts[p * 3 + 1];
        float z = pts[p * 3 + 2];
        sxy[p] = make_float2(x, y);
        szf[p] = z;
    }
    const unsigned bar_l = (unsigned)__cvta_generic_to_shared(mbar);
    if (tid == 0) {
        skey[0] = 0ull; skey[1] = 0ull;
        asm volatile("mbarrier.init.shared.b64 [%0], %1;"
                     :: "r"(bar_l), "r"(FPS_CL) : "memory");
    }
    __syncthreads();
    // Barrier inits must be cluster-visible before any remote arrive.
    asm volatile("barrier.cluster.arrive.aligned;" ::: "memory");
    asm volatile("barrier.cluster.wait.aligned;"   ::: "memory");

    // Precomputed remote addresses (uniform; used by tid0 only).
    const unsigned mbox_l = (unsigned)__cvta_generic_to_shared(mbox);
    unsigned rm_mbox[FPS_CL], rm_bar[FPS_CL];
#pragma unroll
    for (int d = 0; d < FPS_CL; ++d) {
        rm_mbox[d] = mapa_sh(mbox_l + (unsigned)(r * 8), d);  // slot r, buf 0
        rm_bar[d]  = mapa_sh(bar_l, d);
    }

    // This CTA's 4096-point partition -> registers, packed pairs.
    // Slot m (0..7) <-> global index base + m*FPS_NT + tid; pair j packs
    // slots (j, j+NPAIR) so slot order == ascending global index per thread.
    const int base = r * FPS_PART;
    ull rx[FPS_NPAIR], ry[FPS_NPAIR], rz[FPS_NPAIR];
#pragma unroll
    for (int j = 0; j < FPS_NPAIR; ++j) {
        const int pA = base + j * FPS_NT + tid;
        const int pB = pA + FPS_NPAIR * FPS_NT;
        float2 a = sxy[pA], c = sxy[pB];
        rx[j] = pk2(a.x, c.x);
        ry[j] = pk2(a.y, c.y);
        rz[j] = pk2(szf[pA], szf[pB]);
    }
    float md[FPS_PPT];
#pragma unroll
    for (int k = 0; k < FPS_PPT; ++k) md[k] = 1e10f;   // matches jnp 1e10 init

    // First selected point is index 0.
    float qx = sxy[0].x, qy = sxy[0].y, qz = szf[0];
    if (r == 0 && tid == 0) {
        float* o = new_xyz + (size_t)b * Pn * 3;
        o[0] = qx; o[1] = qy; o[2] = qz;
    }

    for (int it = 1; it < Pn; ++it) {
        const ull nqx = pk2(-qx, -qx);
        const ull nqy = pk2(-qy, -qy);
        const ull nqz = pk2(-qz, -qz);

        float vm0 = -1.0f, vm1 = -1.0f;
#pragma unroll
        for (int j = 0; j < FPS_NPAIR; ++j) {
            ull dx = addx2(rx[j], nqx);            // == __fadd_rn(x, -qx)
            ull dy = addx2(ry[j], nqy);
            ull dz = addx2(rz[j], nqz);
            ull s  = addx2(addx2(mulx2(dx, dx), mulx2(dy, dy)), mulx2(dz, dz));
            float d0, d1; upk2(s, d0, d1);
            md[j]             = fminf(md[j],             d0);
            md[j + FPS_NPAIR] = fminf(md[j + FPS_NPAIR], d1);
            vm0 = fmaxf(vm0, md[j]);
            vm1 = fmaxf(vm1, md[j + FPS_NPAIR]);
        }
        const unsigned vb = __float_as_uint(fmaxf(vm0, vm1));

        // Warp max of distance bits (nonneg floats: bit order == float order).
        const unsigned wb = __reduce_max_sync(0xffffffffu, vb);
        unsigned loc = 0xffffffffu;
        if (vb == wb) {
            int bk = 0;
#pragma unroll
            for (int m = FPS_PPT - 1; m >= 0; --m)
                if (__float_as_uint(md[m]) == wb) bk = m;   // smallest slot
            loc = (unsigned)(base + bk * FPS_NT + tid);
        }
        const unsigned lmin = __reduce_min_sync(0xffffffffu, loc);

        const int buf = it & 1;
        if (lane == 0)
            atomicMax(&skey[buf], ((ull)wb << 32) | (0xffffffffu - lmin));
        __syncthreads();

        if (tid == 0) {
            skey[buf ^ 1] = 0ull;                  // reset other buffer
            const ull key = skey[buf];
            const unsigned boff = (unsigned)(buf * FPS_CL * 8);
#pragma unroll
            for (int d = 0; d < FPS_CL; ++d)
                asm volatile("st.shared::cluster.u64 [%0], %1;"
                             :: "r"(rm_mbox[d] + boff), "l"(key) : "memory");
#pragma unroll
            for (int d = 0; d < FPS_CL; ++d)
                asm volatile(
                    "mbarrier.arrive.release.cluster.shared::cluster.b64 _, [%0];"
                    :: "r"(rm_bar[d]) : "memory");
        }
        mbar_wait_acq(bar_l, (unsigned)((it & 1) ^ 1));   // parity 0 at it=1

        // Winner across CTAs: max packed key (max dist, then min index).
        const ull* mb = mbox + buf * FPS_CL;
        ull k0 = mb[0], k1 = mb[1], k2 = mb[2], k3 = mb[3];
        ull kk = k0 > k1 ? k0 : k1;
        ull kl = k2 > k3 ? k2 : k3;
        kk = kk > kl ? kk : kl;
        const int sel = (int)(0xffffffffu - (unsigned)kk);

        float2 qv = sxy[sel];                      // local smem broadcast
        qx = qv.x; qy = qv.y; qz = szf[sel];
        if (r == 0 && tid == 0) {
            float* o = new_xyz + ((size_t)b * Pn + it) * 3;
            o[0] = qx; o[1] = qy; o[2] = qz;
        }
    }
}

// ---------------------------------------------------------------------------
// Kernel 2: Ball query — one warp per center, 8 centers (same batch) per block.
// First nsample in-ball indices in ascending order; pad with first hit (0 if
// none). Early exit once 64 found. Exact (non-contracted) distance + strict <.
// ---------------------------------------------------------------------------
__global__ __launch_bounds__(256)
void ballq_kernel(const float* __restrict__ xyz, const float* __restrict__ new_xyz)
{
    const int wglobal = blockIdx.x * 8 + (threadIdx.x >> 5);  // center id 0..4095
    const int b    = wglobal >> 10;
    const int lane = threadIdx.x & 31;

    const float* pts = xyz + (size_t)b * Nn * 3;
    const float* c   = new_xyz + (size_t)wglobal * 3;
    const float cx = c[0], cy = c[1], cz = c[2];
    int* oidx = g_ball_idx + (size_t)wglobal * Sn;

    const float R2 = (float)(0.3 * 0.3);   // same double->f32 path as JAX

    int  cnt   = 0;
    int  first = 0;
    bool have  = false;

    for (int base = 0; base < Nn; base += 32) {
        const int j = base + lane;
        float x = pts[j * 3 + 0];
        float y = pts[j * 3 + 1];
        float z = pts[j * 3 + 2];
        float dx = __fadd_rn(cx, -x);
        float dy = __fadd_rn(cy, -y);
        float dz = __fadd_rn(cz, -z);
        float d  = __fadd_rn(__fadd_rn(__fmul_rn(dx, dx), __fmul_rn(dy, dy)),
                             __fmul_rn(dz, dz));
        bool in = d < R2;
        unsigned m = __ballot_sync(0xffffffffu, in);
        if (m) {
            if (!have) { first = base + (__ffs(m) - 1); have = true; }
            if (in) {
                int pos = cnt + __popc(m & ((1u << lane) - 1u));
                if (pos < Sn) oidx[pos] = j;
            }
            cnt += __popc(m);
            if (cnt >= Sn) break;
        }
    }
    if (cnt < Sn) {
        for (int s = cnt + lane; s < Sn; s += 32) oidx[s] = first;  // 0 if none
    }
}

// ---------------------------------------------------------------------------
// Kernel 3: gather + MLP(6->64->64->128, relu) + max over samples.
// Block = 128 threads = 2 centers, thread = one sample.
// Weights in smem (W1,W3 transposed; W3 rows padded to 132 floats for
// conflict-free transpose + 16B-aligned float4 broadcast reads).
// Layers 2+3 fused: h2_i consumed immediately, h1[64]+h3[128] in registers.
// ---------------------------------------------------------------------------
constexpr int SW_FLOATS = 384 + 64 + 4096 + 64 + 64 * 132 + 128;  // 13184

__global__ __launch_bounds__(128)
void group_mlp_kernel(const float* __restrict__ xyz, const float* __restrict__ features,
                      const float* __restrict__ W1, const float* __restrict__ b1,
                      const float* __restrict__ W2, const float* __restrict__ b2,
                      const float* __restrict__ W3, const float* __restrict__ b3,
                      const float* __restrict__ new_xyz, float* __restrict__ out_feat)
{
    extern __shared__ float sw[];
    float* w1t = sw;                 // [6][64]   w1t[c*64+o] = W1[o][c]
    float* b1s = w1t + 384;          // [64]
    float* w2s = b1s + 64;           // [64][64]  row i = W2[i][:]
    float* b2s = w2s + 4096;         // [64]
    float* w3t = b2s + 64;           // [64][132] w3t[i*132+o] = W3[o][i]
    float* b3s = w3t + 64 * 132;     // [128]

    const int tid = threadIdx.x;

    for (int j = tid; j < 384; j += 128) {
        int cc = j >> 6, o = j & 63;
        w1t[j] = W1[o * 6 + cc];
    }
    if (tid < 64)  b1s[tid] = b1[tid];
    for (int j = tid; j < 4096; j += 128) w2s[j] = W2[j];
    if (tid < 64)  b2s[tid] = b2[tid];
    for (int j = tid; j < 8192; j += 128) {          // coalesced read, ~4-way STS
        int i = j & 63, o = j >> 6;
        w3t[i * 132 + o] = W3[j];
    }
    if (tid < 128) b3s[tid] = b3[tid];
    __syncthreads();

    const int cl = tid >> 6;                  // which of the 2 centers
    const int s  = tid & 63;                  // sample id
    const int center = blockIdx.x * 2 + cl;
    const int b  = center >> 10;
    const int gi = g_ball_idx[center * Sn + s];

    const float* pb = xyz      + (size_t)b * Nn * 3;
    const float* fb = features + (size_t)b * Nn * 3;
    const float* c  = new_xyz  + (size_t)center * 3;

    float g[6];
    g[0] = pb[gi * 3 + 0] - c[0];
    g[1] = pb[gi * 3 + 1] - c[1];
    g[2] = pb[gi * 3 + 2] - c[2];
    g[3] = fb[gi * 3 + 0];
    g[4] = fb[gi * 3 + 1];
    g[5] = fb[gi * 3 + 2];

    // ---- layer 1 ----
    float h1[64];
#pragma unroll
    for (int o = 0; o < 64; o += 4) {
        float4 bv = *reinterpret_cast<const float4*>(b1s + o);
        h1[o] = bv.x; h1[o + 1] = bv.y; h1[o + 2] = bv.z; h1[o + 3] = bv.w;
    }
#pragma unroll
    for (int cc = 0; cc < 6; ++cc) {
        float gv = g[cc];
        const float4* wr = reinterpret_cast<const float4*>(w1t + cc * 64);
#pragma unroll
        for (int o = 0; o < 64; o += 4) {
            float4 w = wr[o >> 2];
            h1[o]     += w.x * gv;
            h1[o + 1] += w.y * gv;
            h1[o + 2] += w.z * gv;
            h1[o + 3] += w.w * gv;
        }
    }
#pragma unroll
    for (int o = 0; o < 64; ++o) h1[o] = fmaxf(h1[o], 0.0f);

    // ---- fused layers 2+3 ----
    float h3[128];
#pragma unroll
    for (int o = 0; o < 128; o += 4) {
        float4 bv = *reinterpret_cast<const float4*>(b3s + o);
        h3[o] = bv.x; h3[o + 1] = bv.y; h3[o + 2] = bv.z; h3[o + 3] = bv.w;
    }

    for (int i = 0; i < 64; ++i) {
        const float4* w2r = reinterpret_cast<const float4*>(w2s + (i << 6));
        float a0 = 0.f, a1 = 0.f, a2 = 0.f, a3 = 0.f;
#pragma unroll
        for (int j = 0; j < 64; j += 16) {
            float4 wA = w2r[(j >> 2) + 0];
            float4 wB = w2r[(j >> 2) + 1];
            float4 wC = w2r[(j >> 2) + 2];
            float4 wD = w2r[(j >> 2) + 3];
            a0 += wA.x * h1[j + 0]  + wA.y * h1[j + 1]  + wA.z * h1[j + 2]  + wA.w * h1[j + 3];
            a1 += wB.x * h1[j + 4]  + wB.y * h1[j + 5]  + wB.z * h1[j + 6]  + wB.w * h1[j + 7];
            a2 += wC.x * h1[j + 8]  + wC.y * h1[j + 9]  + wC.z * h1[j + 10] + wC.w * h1[j + 11];
            a3 += wD.x * h1[j + 12] + wD.y * h1[j + 13] + wD.z * h1[j + 14] + wD.w * h1[j + 15];
        }
        float h2i = fmaxf(((a0 + a1) + (a2 + a3)) + b2s[i], 0.0f);

        const float4* w3r = reinterpret_cast<const float4*>(w3t + i * 132);
#pragma unroll
        for (int o = 0; o < 128; o += 4) {
            float4 w = w3r[o >> 2];
            h3[o]     += w.x * h2i;
            h3[o + 1] += w.y * h2i;
            h3[o + 2] += w.z * h2i;
            h3[o + 3] += w.w * h2i;
        }
    }

#pragma unroll
    for (int o = 0; o < 128; ++o) h3[o] = fmaxf(h3[o], 0.0f);

    // ---- max over 64 samples (2 warps per center) ----
#pragma unroll
    for (int o = 0; o < 128; ++o) {
#pragma unroll
        for (int off = 16; off > 0; off >>= 1)
            h3[o] = fmaxf(h3[o], __shfl_down_sync(0xffffffffu, h3[o], off));
    }
    __shared__ float red[4][128];
    const int wid = tid >> 5, lane = tid & 31;
    if (lane == 0) {
#pragma unroll
        for (int o = 0; o < 128; ++o) red[wid][o] = h3[o];
    }
    __syncthreads();
    for (int t = tid; t < 256; t += 128) {
        int cc = t >> 7, oo = t & 127;
        float v = fmaxf(red[2 * cc][oo], red[2 * cc + 1][oo]);
        int ctr = blockIdx.x * 2 + cc;
        int bb = ctr >> 10, pp = ctr & 1023;
        out_feat[(size_t)bb * (128 * Pn) + (size_t)oo * Pn + pp] = v;
    }
}

// ---------------------------------------------------------------------------
// Launch: fps (clustered) -> ball query -> group+MLP.
// Output = [new_xyz | new_features].
// ---------------------------------------------------------------------------
extern "C" void kernel_launch(void* const* d_in, const int* in_sizes, int n_in,
                              void* d_out, int out_size)
{
    (void)in_sizes; (void)n_in; (void)out_size;

    const float* xyz      = (const float*)d_in[0];
    const float* features = (const float*)d_in[1];
    const float* W1 = (const float*)d_in[2];
    const float* b1 = (const float*)d_in[3];
    const float* W2 = (const float*)d_in[4];
    const float* b2 = (const float*)d_in[5];
    const float* W3 = (const float*)d_in[6];
    const float* b3 = (const float*)d_in[7];

    float* out      = (float*)d_out;
    float* new_xyz  = out;                         // (B, P, 3)
    float* out_feat = out + (size_t)Bn * Pn * 3;   // (B, 128, P)

    const int mlp_smem = SW_FLOATS * (int)sizeof(float);      // 52736

    cudaFuncSetAttribute(fps_kernel,
                         cudaFuncAttributeMaxDynamicSharedMemorySize, FPS_SMEM);
    cudaFuncSetAttribute(group_mlp_kernel,
                         cudaFuncAttributeMaxDynamicSharedMemorySize, mlp_smem);

    fps_kernel<<<Bn * FPS_CL, FPS_NT, FPS_SMEM>>>(xyz, new_xyz);
    ballq_kernel<<<(Bn * Pn) / 8, 256>>>(xyz, new_xyz);
    group_mlp_kernel<<<(Bn * Pn) / 2, 128, mlp_smem>>>(
        xyz, features, W1, b1, W2, b2, W3, b3, new_xyz, out_feat);
}

// round 9
// speedup vs baseline: 1.5169x; 1.5169x over previous
#include <cuda_runtime.h>

// Problem constants (fixed shapes from the reference)
constexpr int Bn = 4;       // batch
constexpr int Nn = 16384;   // points per cloud
constexpr int Pn = 1024;    // npoint (FPS samples)
constexpr int Sn = 64;      // nsample (ball query)

// Scratch: ball query indices (B,P,S). 1 MB.
__device__ int g_ball_idx[Bn * Pn * Sn];

// ---- packed f32x2 helpers (sm_100+). Per-lane semantics identical to
// __fadd_rn / __fmul_rn, so FPS distances stay bit-exact vs the scalar path.
typedef unsigned long long ull;
__device__ __forceinline__ ull pk2(float lo, float hi) {
    ull r; asm("mov.b64 %0,{%1,%2};" : "=l"(r) : "f"(lo), "f"(hi)); return r;
}
__device__ __forceinline__ void upk2(ull v, float& lo, float& hi) {
    asm("mov.b64 {%0,%1},%2;" : "=f"(lo), "=f"(hi) : "l"(v));
}
__device__ __forceinline__ ull addx2(ull a, ull b) {
    ull r; asm("add.rn.f32x2 %0,%1,%2;" : "=l"(r) : "l"(a), "l"(b)); return r;
}
__device__ __forceinline__ ull mulx2(ull a, ull b) {
    ull r; asm("mul.rn.f32x2 %0,%1,%2;" : "=l"(r) : "l"(a), "l"(b)); return r;
}
__device__ __forceinline__ unsigned mapa_sh(unsigned addr, int rank) {
    unsigned r;
    asm("mapa.shared::cluster.u32 %0, %1, %2;" : "=r"(r) : "r"(addr), "r"(rank));
    return r;
}

// ---------------------------------------------------------------------------
// Kernel 1: Furthest Point Sampling — 4-CTA cluster per batch.
// Each CTA (512 threads) owns 4096 points fully in registers (packed f32x2);
// full-cloud coord copy in smem for the per-iter broadcast read.
// Per iteration (ONE __syncthreads, NO atomics, NO barrier.cluster):
//   redux.max (dist bits) + gated redux.min (global idx) per warp,
//   lane0 -> skey16[wid] (16 distinct slots), BAR,
//   tid0 max-reduces 16 keys, stamps iteration tag (bits 14..23) and
//   st.shared::cluster's the key into all 4 CTAs' mailboxes (double-buffered),
//   every thread polls its LOCAL mailbox until all 4 slots carry the tag,
//   then takes the max key: (max dist, then min global idx) == jnp.argmax.
// The poll doubles as the intra-CTA barrier for the next iteration (no thread
// passes it before local tid0 stored, and tid0 stores after reading skey16).
// ---------------------------------------------------------------------------
constexpr int FPS_CL   = 4;                 // CTAs per batch (cluster size)
constexpr int FPS_PART = Nn / FPS_CL;       // 4096 points per CTA
constexpr int FPS_NT   = 512;               // threads per CTA
constexpr int FPS_PPT  = FPS_PART / FPS_NT; // 8 points per thread
constexpr int FPS_NPAIR = FPS_PPT / 2;      // 4 packed pairs per thread
// smem: float sxy[2*Nn] + szf[Nn], then ull skey16[16] + mbox[2][4]
constexpr int FPS_SMEM = 3 * Nn * 4 + 24 * 8;

__global__ __launch_bounds__(FPS_NT, 1) __cluster_dims__(FPS_CL, 1, 1)
void fps_kernel(const float* __restrict__ xyz, float* __restrict__ new_xyz)
{
    const int b = blockIdx.x / FPS_CL;
    const int r = blockIdx.x % FPS_CL;     // cluster rank
    const float* pts = xyz + (size_t)b * Nn * 3;

    extern __shared__ float sm[];
    float2* sxy    = reinterpret_cast<float2*>(sm);   // [Nn]
    float*  szf    = sm + 2 * Nn;                     // [Nn]
    ull*    skey16 = reinterpret_cast<ull*>(sm + 3 * Nn);  // [16]
    ull*    mbox   = skey16 + 16;                     // [2][4]

    const int tid  = threadIdx.x;
    const int lane = tid & 31;
    const int wid  = tid >> 5;

    // Stage the full cloud into this CTA's smem (for broadcasts).
    for (int p = tid; p < Nn; p += FPS_NT) {
        float x = pts[p * 3 + 0];
        float y = pts[p * 3 + 1];
        float z = pts[p * 3 + 2];
        sxy[p] = make_float2(x, y);
        szf[p] = z;
    }
    if (tid < 8) mbox[tid] = 0ull;         // tag 0 (never used: it >= 1)
    __syncthreads();
    // Mailbox init must be cluster-visible before any remote store (startup
    // only — no cluster barrier inside the loop).
    asm volatile("barrier.cluster.arrive.aligned;" ::: "memory");
    asm volatile("barrier.cluster.wait.aligned;"   ::: "memory");

    // Precomputed remote mailbox addresses (used by tid0 only).
    const unsigned mbox_l = (unsigned)__cvta_generic_to_shared(mbox);
    unsigned rm_mbox[FPS_CL];
#pragma unroll
    for (int d = 0; d < FPS_CL; ++d)
        rm_mbox[d] = mapa_sh(mbox_l + (unsigned)(r * 8), d);  // slot r, buf 0

    // This CTA's 4096-point partition -> registers, packed pairs.
    // Slot m (0..7) <-> global index base + m*FPS_NT + tid; pair j packs
    // slots (j, j+NPAIR) so slot order == ascending global index per thread.
    const int base = r * FPS_PART;
    ull rx[FPS_NPAIR], ry[FPS_NPAIR], rz[FPS_NPAIR];
#pragma unroll
    for (int j = 0; j < FPS_NPAIR; ++j) {
        const int pA = base + j * FPS_NT + tid;
        const int pB = pA + FPS_NPAIR * FPS_NT;
        float2 a = sxy[pA], c = sxy[pB];
        rx[j] = pk2(a.x, c.x);
        ry[j] = pk2(a.y, c.y);
        rz[j] = pk2(szf[pA], szf[pB]);
    }
    float md[FPS_PPT];
#pragma unroll
    for (int k = 0; k < FPS_PPT; ++k) md[k] = 1e10f;   // matches jnp 1e10 init

    // First selected point is index 0.
    float qx = sxy[0].x, qy = sxy[0].y, qz = szf[0];
    if (r == 0 && tid == 0) {
        float* o = new_xyz + (size_t)b * Pn * 3;
        o[0] = qx; o[1] = qy; o[2] = qz;
    }

    volatile ull* vmbox = mbox;

    for (int it = 1; it < Pn; ++it) {
        const ull nqx = pk2(-qx, -qx);
        const ull nqy = pk2(-qy, -qy);
        const ull nqz = pk2(-qz, -qz);

        float vm0 = -1.0f, vm1 = -1.0f;
#pragma unroll
        for (int j = 0; j < FPS_NPAIR; ++j) {
            ull dx = addx2(rx[j], nqx);            // == __fadd_rn(x, -qx)
            ull dy = addx2(ry[j], nqy);
            ull dz = addx2(rz[j], nqz);
            ull s  = addx2(addx2(mulx2(dx, dx), mulx2(dy, dy)), mulx2(dz, dz));
            float d0, d1; upk2(s, d0, d1);
            md[j]             = fminf(md[j],             d0);
            md[j + FPS_NPAIR] = fminf(md[j + FPS_NPAIR], d1);
            vm0 = fmaxf(vm0, md[j]);
            vm1 = fmaxf(vm1, md[j + FPS_NPAIR]);
        }
        const unsigned vb = __float_as_uint(fmaxf(vm0, vm1));

        // Warp max of distance bits (nonneg floats: bit order == float order),
        // then min global index among the warp's winners (first-match tiebreak).
        const unsigned wb = __reduce_max_sync(0xffffffffu, vb);
        unsigned loc = 0xffffffffu;
        if (vb == wb) {
            int bk = 0;
#pragma unroll
            for (int m = FPS_PPT - 1; m >= 0; --m)
                if (__float_as_uint(md[m]) == wb) bk = m;   // smallest slot
            loc = (unsigned)(base + bk * FPS_NT + tid);
        }
        const unsigned lmin = __reduce_min_sync(0xffffffffu, loc);  // <= 16383

        if (lane == 0)
            skey16[wid] = ((ull)wb << 32) | (unsigned)(0x3FFF - lmin);
        __syncthreads();

        const int buf = it & 1;
        const unsigned tag = (unsigned)(it & 0x3FF);
        if (tid == 0) {
            const ulonglong2* k2p = reinterpret_cast<const ulonglong2*>(skey16);
            ull bk = 0ull;
#pragma unroll
            for (int q = 0; q < 8; ++q) {
                ulonglong2 kv = k2p[q];
                ull km = kv.x > kv.y ? kv.x : kv.y;
                bk = km > bk ? km : bk;
            }
            bk |= (ull)tag << 14;                  // idx bits 0..13, tag 14..23
            const unsigned boff = (unsigned)(buf * FPS_CL * 8);
#pragma unroll
            for (int d = 0; d < FPS_CL; ++d)
                asm volatile("st.shared::cluster.u64 [%0], %1;"
                             :: "r"(rm_mbox[d] + boff), "l"(bk) : "memory");
        }

        // Poll local mailbox until all 4 slots carry this iteration's tag.
        ull k0, k1, k2, k3;
        for (;;) {
            k0 = vmbox[buf * 4 + 0];
            k1 = vmbox[buf * 4 + 1];
            k2 = vmbox[buf * 4 + 2];
            k3 = vmbox[buf * 4 + 3];
            unsigned t0 = (unsigned)(k0 >> 14) & 0x3FF;
            unsigned t1 = (unsigned)(k1 >> 14) & 0x3FF;
            unsigned t2 = (unsigned)(k2 >> 14) & 0x3FF;
            unsigned t3 = (unsigned)(k3 >> 14) & 0x3FF;
            if (((t0 ^ tag) | (t1 ^ tag) | (t2 ^ tag) | (t3 ^ tag)) == 0u)
                break;
        }

        // Winner across CTAs: max packed key (max dist, then min index).
        ull kk = k0 > k1 ? k0 : k1;
        ull kl = k2 > k3 ? k2 : k3;
        kk = kk > kl ? kk : kl;
        const int sel = (int)(0x3FFFu - ((unsigned)kk & 0x3FFFu));

        float2 qv = sxy[sel];                      // local smem broadcast
        qx = qv.x; qy = qv.y; qz = szf[sel];
        if (r == 0 && tid == 0) {
            float* o = new_xyz + ((size_t)b * Pn + it) * 3;
            o[0] = qx; o[1] = qy; o[2] = qz;
        }
    }

    // No CTA may exit while peers might still write into its mailbox.
    asm volatile("barrier.cluster.arrive.aligned;" ::: "memory");
    asm volatile("barrier.cluster.wait.aligned;"   ::: "memory");
}

// ---------------------------------------------------------------------------
// Kernel 2: Ball query — one warp per center, 8 centers (same batch) per block.
// First nsample in-ball indices in ascending order; pad with first hit (0 if
// none). Early exit once 64 found. Exact (non-contracted) distance + strict <.
// ---------------------------------------------------------------------------
__global__ __launch_bounds__(256)
void ballq_kernel(const float* __restrict__ xyz, const float* __restrict__ new_xyz)
{
    const int wglobal = blockIdx.x * 8 + (threadIdx.x >> 5);  // center id 0..4095
    const int b    = wglobal >> 10;
    const int lane = threadIdx.x & 31;

    const float* pts = xyz + (size_t)b * Nn * 3;
    const float* c   = new_xyz + (size_t)wglobal * 3;
    const float cx = c[0], cy = c[1], cz = c[2];
    int* oidx = g_ball_idx + (size_t)wglobal * Sn;

    const float R2 = (float)(0.3 * 0.3);   // same double->f32 path as JAX

    int  cnt   = 0;
    int  first = 0;
    bool have  = false;

    for (int base = 0; base < Nn; base += 32) {
        const int j = base + lane;
        float x = pts[j * 3 + 0];
        float y = pts[j * 3 + 1];
        float z = pts[j * 3 + 2];
        float dx = __fadd_rn(cx, -x);
        float dy = __fadd_rn(cy, -y);
        float dz = __fadd_rn(cz, -z);
        float d  = __fadd_rn(__fadd_rn(__fmul_rn(dx, dx), __fmul_rn(dy, dy)),
                             __fmul_rn(dz, dz));
        bool in = d < R2;
        unsigned m = __ballot_sync(0xffffffffu, in);
        if (m) {
            if (!have) { first = base + (__ffs(m) - 1); have = true; }
            if (in) {
                int pos = cnt + __popc(m & ((1u << lane) - 1u));
                if (pos < Sn) oidx[pos] = j;
            }
            cnt += __popc(m);
            if (cnt >= Sn) break;
        }
    }
    if (cnt < Sn) {
        for (int s = cnt + lane; s < Sn; s += 32) oidx[s] = first;  // 0 if none
    }
}

// ---------------------------------------------------------------------------
// Kernel 3: gather + MLP(6->64->64->128, relu) + max over samples.
// Block = 128 threads = 2 centers, thread = one sample.
// Weights in smem (W1,W3 transposed; W3 rows padded to 132 floats for
// conflict-free transpose + 16B-aligned float4 broadcast reads).
// Layers 2+3 fused: h2_i consumed immediately, h1[64]+h3[128] in registers.
// ---------------------------------------------------------------------------
constexpr int SW_FLOATS = 384 + 64 + 4096 + 64 + 64 * 132 + 128;  // 13184

__global__ __launch_bounds__(128)
void group_mlp_kernel(const float* __restrict__ xyz, const float* __restrict__ features,
                      const float* __restrict__ W1, const float* __restrict__ b1,
                      const float* __restrict__ W2, const float* __restrict__ b2,
                      const float* __restrict__ W3, const float* __restrict__ b3,
                      const float* __restrict__ new_xyz, float* __restrict__ out_feat)
{
    extern __shared__ float sw[];
    float* w1t = sw;                 // [6][64]   w1t[c*64+o] = W1[o][c]
    float* b1s = w1t + 384;          // [64]
    float* w2s = b1s + 64;           // [64][64]  row i = W2[i][:]
    float* b2s = w2s + 4096;         // [64]
    float* w3t = b2s + 64;           // [64][132] w3t[i*132+o] = W3[o][i]
    float* b3s = w3t + 64 * 132;     // [128]

    const int tid = threadIdx.x;

    for (int j = tid; j < 384; j += 128) {
        int cc = j >> 6, o = j & 63;
        w1t[j] = W1[o * 6 + cc];
    }
    if (tid < 64)  b1s[tid] = b1[tid];
    for (int j = tid; j < 4096; j += 128) w2s[j] = W2[j];
    if (tid < 64)  b2s[tid] = b2[tid];
    for (int j = tid; j < 8192; j += 128) {          // coalesced read, ~4-way STS
        int i = j & 63, o = j >> 6;
        w3t[i * 132 + o] = W3[j];
    }
    if (tid < 128) b3s[tid] = b3[tid];
    __syncthreads();

    const int cl = tid >> 6;                  // which of the 2 centers
    const int s  = tid & 63;                  // sample id
    const int center = blockIdx.x * 2 + cl;
    const int b  = center >> 10;
    const int gi = g_ball_idx[center * Sn + s];

    const float* pb = xyz      + (size_t)b * Nn * 3;
    const float* fb = features + (size_t)b * Nn * 3;
    const float* c  = new_xyz  + (size_t)center * 3;

    float g[6];
    g[0] = pb[gi * 3 + 0] - c[0];
    g[1] = pb[gi * 3 + 1] - c[1];
    g[2] = pb[gi * 3 + 2] - c[2];
    g[3] = fb[gi * 3 + 0];
    g[4] = fb[gi * 3 + 1];
    g[5] = fb[gi * 3 + 2];

    // ---- layer 1 ----
    float h1[64];
#pragma unroll
    for (int o = 0; o < 64; o += 4) {
        float4 bv = *reinterpret_cast<const float4*>(b1s + o);
        h1[o] = bv.x; h1[o + 1] = bv.y; h1[o + 2] = bv.z; h1[o + 3] = bv.w;
    }
#pragma unroll
    for (int cc = 0; cc < 6; ++cc) {
        float gv = g[cc];
        const float4* wr = reinterpret_cast<const float4*>(w1t + cc * 64);
#pragma unroll
        for (int o = 0; o < 64; o += 4) {
            float4 w = wr[o >> 2];
            h1[o]     += w.x * gv;
            h1[o + 1] += w.y * gv;
            h1[o + 2] += w.z * gv;
            h1[o + 3] += w.w * gv;
        }
    }
#pragma unroll
    for (int o = 0; o < 64; ++o) h1[o] = fmaxf(h1[o], 0.0f);

    // ---- fused layers 2+3 ----
    float h3[128];
#pragma unroll
    for (int o = 0; o < 128; o += 4) {
        float4 bv = *reinterpret_cast<const float4*>(b3s + o);
        h3[o] = bv.x; h3[o + 1] = bv.y; h3[o + 2] = bv.z; h3[o + 3] = bv.w;
    }

    for (int i = 0; i < 64; ++i) {
        const float4* w2r = reinterpret_cast<const float4*>(w2s + (i << 6));
        float a0 = 0.f, a1 = 0.f, a2 = 0.f, a3 = 0.f;
#pragma unroll
        for (int j = 0; j < 64; j += 16) {
            float4 wA = w2r[(j >> 2) + 0];
            float4 wB = w2r[(j >> 2) + 1];
            float4 wC = w2r[(j >> 2) + 2];
            float4 wD = w2r[(j >> 2) + 3];
            a0 += wA.x * h1[j + 0]  + wA.y * h1[j + 1]  + wA.z * h1[j + 2]  + wA.w * h1[j + 3];
            a1 += wB.x * h1[j + 4]  + wB.y * h1[j + 5]  + wB.z * h1[j + 6]  + wB.w * h1[j + 7];
            a2 += wC.x * h1[j + 8]  + wC.y * h1[j + 9]  + wC.z * h1[j + 10] + wC.w * h1[j + 11];
            a3 += wD.x * h1[j + 12] + wD.y * h1[j + 13] + wD.z * h1[j + 14] + wD.w * h1[j + 15];
        }
        float h2i = fmaxf(((a0 + a1) + (a2 + a3)) + b2s[i], 0.0f);

        const float4* w3r = reinterpret_cast<const float4*>(w3t + i * 132);
#pragma unroll
        for (int o = 0; o < 128; o += 4) {
            float4 w = w3r[o >> 2];
            h3[o]     += w.x * h2i;
            h3[o + 1] += w.y * h2i;
            h3[o + 2] += w.z * h2i;
            h3[o + 3] += w.w * h2i;
        }
    }

#pragma unroll
    for (int o = 0; o < 128; ++o) h3[o] = fmaxf(h3[o], 0.0f);

    // ---- max over 64 samples (2 warps per center) ----
#pragma unroll
    for (int o = 0; o < 128; ++o) {
#pragma unroll
        for (int off = 16; off > 0; off >>= 1)
            h3[o] = fmaxf(h3[o], __shfl_down_sync(0xffffffffu, h3[o], off));
    }
    __shared__ float red[4][128];
    const int wid = tid >> 5, lane = tid & 31;
    if (lane == 0) {
#pragma unroll
        for (int o = 0; o < 128; ++o) red[wid][o] = h3[o];
    }
    __syncthreads();
    for (int t = tid; t < 256; t += 128) {
        int cc = t >> 7, oo = t & 127;
        float v = fmaxf(red[2 * cc][oo], red[2 * cc + 1][oo]);
        int ctr = blockIdx.x * 2 + cc;
        int bb = ctr >> 10, pp = ctr & 1023;
        out_feat[(size_t)bb * (128 * Pn) + (size_t)oo * Pn + pp] = v;
    }
}

// ---------------------------------------------------------------------------
// Launch: fps (clustered) -> ball query -> group+MLP.
// Output = [new_xyz | new_features].
// ---------------------------------------------------------------------------
extern "C" void kernel_launch(void* const* d_in, const int* in_sizes, int n_in,
                              void* d_out, int out_size)
{
    (void)in_sizes; (void)n_in; (void)out_size;

    const float* xyz      = (const float*)d_in[0];
    const float* features = (const float*)d_in[1];
    const float* W1 = (const float*)d_in[2];
    const float* b1 = (const float*)d_in[3];
    const float* W2 = (const float*)d_in[4];
    const float* b2 = (const float*)d_in[5];
    const float* W3 = (const float*)d_in[6];
    const float* b3 = (const float*)d_in[7];

    float* out      = (float*)d_out;
    float* new_xyz  = out;                         // (B, P, 3)
    float* out_feat = out + (size_t)Bn * Pn * 3;   // (B, 128, P)

    const int mlp_smem = SW_FLOATS * (int)sizeof(float);      // 52736

    cudaFuncSetAttribute(fps_kernel,
                         cudaFuncAttributeMaxDynamicSharedMemorySize, FPS_SMEM);
    cudaFuncSetAttribute(group_mlp_kernel,
                         cudaFuncAttributeMaxDynamicSharedMemorySize, mlp_smem);

    fps_kernel<<<Bn * FPS_CL, FPS_NT, FPS_SMEM>>>(xyz, new_xyz);
    ballq_kernel<<<(Bn * Pn) / 8, 256>>>(xyz, new_xyz);
    group_mlp_kernel<<<(Bn * Pn) / 2, 128, mlp_smem>>>(
        xyz, features, W1, b1, W2, b2, W3, b3, new_xyz, out_feat);
}

// round 10
// speedup vs baseline: 1.7713x; 1.1677x over previous
#include <cuda_runtime.h>

// Problem constants (fixed shapes from the reference)
constexpr int Bn = 4;       // batch
constexpr int Nn = 16384;   // points per cloud
constexpr int Pn = 1024;    // npoint (FPS samples)
constexpr int Sn = 64;      // nsample (ball query)

// Scratch: ball query indices (B,P,S). 1 MB.
__device__ int g_ball_idx[Bn * Pn * Sn];

// ---- packed f32x2 helpers (sm_100+). Per-lane semantics identical to
// __fadd_rn / __fmul_rn, so FPS distances stay bit-exact vs the scalar path.
typedef unsigned long long ull;
__device__ __forceinline__ ull pk2(float lo, float hi) {
    ull r; asm("mov.b64 %0,{%1,%2};" : "=l"(r) : "f"(lo), "f"(hi)); return r;
}
__device__ __forceinline__ void upk2(ull v, float& lo, float& hi) {
    asm("mov.b64 {%0,%1},%2;" : "=f"(lo), "=f"(hi) : "l"(v));
}
__device__ __forceinline__ ull addx2(ull a, ull b) {
    ull r; asm("add.rn.f32x2 %0,%1,%2;" : "=l"(r) : "l"(a), "l"(b)); return r;
}
__device__ __forceinline__ ull mulx2(ull a, ull b) {
    ull r; asm("mul.rn.f32x2 %0,%1,%2;" : "=l"(r) : "l"(a), "l"(b)); return r;
}
__device__ __forceinline__ unsigned mapa_sh(unsigned addr, int rank) {
    unsigned r;
    asm("mapa.shared::cluster.u32 %0, %1, %2;" : "=r"(r) : "r"(addr), "r"(rank));
    return r;
}
__device__ __forceinline__ ull umax64(ull a, ull b) { return a > b ? a : b; }

// ---------------------------------------------------------------------------
// Kernel 1: Furthest Point Sampling — 8-CTA cluster per batch.
// Each CTA (256 threads) owns 2048 points fully in registers (packed f32x2);
// full-cloud coord copy in smem for the per-iter broadcast read.
// Per iteration (ONE __syncthreads, NO atomics, NO barrier.cluster):
//   redux.max (dist bits) + gated redux.min (global idx) per warp,
//   lane0 -> skey8[wid] (8 distinct slots), BAR,
//   tid0 max-reduces 8 keys, stamps iteration tag (bits 14..23) and
//   st.shared::cluster's the key into all 8 CTAs' mailboxes (double-buffered),
//   every thread polls its LOCAL mailbox (4x LDS.128) until all 8 slots carry
//   the tag, then max key => (max dist, then min global idx) == jnp.argmax.
// ---------------------------------------------------------------------------
constexpr int FPS_CL   = 8;                 // CTAs per batch (cluster size)
constexpr int FPS_PART = Nn / FPS_CL;       // 2048 points per CTA
constexpr int FPS_NT   = 256;               // threads per CTA
constexpr int FPS_PPT  = FPS_PART / FPS_NT; // 8 points per thread
constexpr int FPS_NPAIR = FPS_PPT / 2;      // 4 packed pairs per thread
// smem: float sxy[2*Nn] + szf[Nn], then ull skey8[8] + mbox[2][8]
constexpr int FPS_SMEM = 3 * Nn * 4 + 24 * 8;

__global__ __launch_bounds__(FPS_NT, 1) __cluster_dims__(FPS_CL, 1, 1)
void fps_kernel(const float* __restrict__ xyz, float* __restrict__ new_xyz)
{
    const int b = blockIdx.x / FPS_CL;
    const int r = blockIdx.x % FPS_CL;     // cluster rank
    const float* pts = xyz + (size_t)b * Nn * 3;

    extern __shared__ float sm[];
    float2* sxy   = reinterpret_cast<float2*>(sm);   // [Nn]
    float*  szf   = sm + 2 * Nn;                     // [Nn]
    ull*    skey8 = reinterpret_cast<ull*>(sm + 3 * Nn);  // [8]
    ull*    mbox  = skey8 + 8;                       // [2][8]

    const int tid  = threadIdx.x;
    const int lane = tid & 31;
    const int wid  = tid >> 5;

    // Stage the full cloud into this CTA's smem (for broadcasts).
    for (int p = tid; p < Nn; p += FPS_NT) {
        float x = pts[p * 3 + 0];
        float y = pts[p * 3 + 1];
        float z = pts[p * 3 + 2];
        sxy[p] = make_float2(x, y);
        szf[p] = z;
    }
    if (tid < 16) mbox[tid] = 0ull;        // tag 0 (never used: it >= 1)
    __syncthreads();
    // Mailbox init must be cluster-visible before any remote store (startup
    // only — no cluster barrier inside the loop).
    asm volatile("barrier.cluster.arrive.aligned;" ::: "memory");
    asm volatile("barrier.cluster.wait.aligned;"   ::: "memory");

    // Precomputed remote mailbox addresses (used by tid0 only).
    const unsigned mbox_l = (unsigned)__cvta_generic_to_shared(mbox);
    unsigned rm_mbox[FPS_CL];
#pragma unroll
    for (int d = 0; d < FPS_CL; ++d)
        rm_mbox[d] = mapa_sh(mbox_l + (unsigned)(r * 8), d);  // slot r, buf 0

    // This CTA's 2048-point partition -> registers, packed pairs.
    // Slot m (0..7) <-> global index base + m*FPS_NT + tid; pair j packs
    // slots (j, j+NPAIR) so slot order == ascending global index per thread.
    const int base = r * FPS_PART;
    ull rx[FPS_NPAIR], ry[FPS_NPAIR], rz[FPS_NPAIR];
#pragma unroll
    for (int j = 0; j < FPS_NPAIR; ++j) {
        const int pA = base + j * FPS_NT + tid;
        const int pB = pA + FPS_NPAIR * FPS_NT;
        float2 a = sxy[pA], c = sxy[pB];
        rx[j] = pk2(a.x, c.x);
        ry[j] = pk2(a.y, c.y);
        rz[j] = pk2(szf[pA], szf[pB]);
    }
    float md[FPS_PPT];
#pragma unroll
    for (int k = 0; k < FPS_PPT; ++k) md[k] = 1e10f;   // matches jnp 1e10 init

    // First selected point is index 0.
    float qx = sxy[0].x, qy = sxy[0].y, qz = szf[0];
    if (r == 0 && tid == 0) {
        float* o = new_xyz + (size_t)b * Pn * 3;
        o[0] = qx; o[1] = qy; o[2] = qz;
    }

    for (int it = 1; it < Pn; ++it) {
        const ull nqx = pk2(-qx, -qx);
        const ull nqy = pk2(-qy, -qy);
        const ull nqz = pk2(-qz, -qz);

        float vm0 = -1.0f, vm1 = -1.0f;
#pragma unroll
        for (int j = 0; j < FPS_NPAIR; ++j) {
            ull dx = addx2(rx[j], nqx);            // == __fadd_rn(x, -qx)
            ull dy = addx2(ry[j], nqy);
            ull dz = addx2(rz[j], nqz);
            ull s  = addx2(addx2(mulx2(dx, dx), mulx2(dy, dy)), mulx2(dz, dz));
            float d0, d1; upk2(s, d0, d1);
            md[j]             = fminf(md[j],             d0);
            md[j + FPS_NPAIR] = fminf(md[j + FPS_NPAIR], d1);
            vm0 = fmaxf(vm0, md[j]);
            vm1 = fmaxf(vm1, md[j + FPS_NPAIR]);
        }
        const unsigned vb = __float_as_uint(fmaxf(vm0, vm1));

        // Warp max of distance bits (nonneg floats: bit order == float order),
        // then min global index among the warp's winners (first-match tiebreak).
        const unsigned wb = __reduce_max_sync(0xffffffffu, vb);
        unsigned loc = 0xffffffffu;
        if (vb == wb) {
            int bk = 0;
#pragma unroll
            for (int m = FPS_PPT - 1; m >= 0; --m)
                if (__float_as_uint(md[m]) == wb) bk = m;   // smallest slot
            loc = (unsigned)(base + bk * FPS_NT + tid);
        }
        const unsigned lmin = __reduce_min_sync(0xffffffffu, loc);  // <= 16383

        if (lane == 0)
            skey8[wid] = ((ull)wb << 32) | (unsigned)(0x3FFF - lmin);
        __syncthreads();

        const int buf = it & 1;
        const unsigned tag = (unsigned)(it & 0x3FF);
        if (tid == 0) {
            const ulonglong2* k2p = reinterpret_cast<const ulonglong2*>(skey8);
            ulonglong2 a0 = k2p[0], a1 = k2p[1], a2 = k2p[2], a3 = k2p[3];
            ull bk = umax64(umax64(umax64(a0.x, a0.y), umax64(a1.x, a1.y)),
                            umax64(umax64(a2.x, a2.y), umax64(a3.x, a3.y)));
            bk |= (ull)tag << 14;                  // idx bits 0..13, tag 14..23
            const unsigned boff = (unsigned)(buf * FPS_CL * 8);
#pragma unroll
            for (int d = 0; d < FPS_CL; ++d)
                asm volatile("st.shared::cluster.u64 [%0], %1;"
                             :: "r"(rm_mbox[d] + boff), "l"(bk) : "memory");
        }

        // Poll local mailbox (4x LDS.128) until all 8 slots carry this tag.
        const unsigned mba = mbox_l + (unsigned)(buf * FPS_CL * 8);
        ull k[8];
        for (;;) {
            asm volatile("ld.volatile.shared.v2.u64 {%0,%1},[%2];"
                         : "=l"(k[0]), "=l"(k[1]) : "r"(mba));
            asm volatile("ld.volatile.shared.v2.u64 {%0,%1},[%2];"
                         : "=l"(k[2]), "=l"(k[3]) : "r"(mba + 16));
            asm volatile("ld.volatile.shared.v2.u64 {%0,%1},[%2];"
                         : "=l"(k[4]), "=l"(k[5]) : "r"(mba + 32));
            asm volatile("ld.volatile.shared.v2.u64 {%0,%1},[%2];"
                         : "=l"(k[6]), "=l"(k[7]) : "r"(mba + 48));
            unsigned bad = 0;
#pragma unroll
            for (int q = 0; q < 8; ++q)
                bad |= ((unsigned)(k[q] >> 14) & 0x3FFu) ^ tag;
            if (!bad) break;
        }

        // Winner across CTAs: max packed key (max dist, then min index).
        ull kk = umax64(umax64(umax64(k[0], k[1]), umax64(k[2], k[3])),
                        umax64(umax64(k[4], k[5]), umax64(k[6], k[7])));
        const int sel = (int)(0x3FFFu - ((unsigned)kk & 0x3FFFu));

        float2 qv = sxy[sel];                      // local smem broadcast
        qx = qv.x; qy = qv.y; qz = szf[sel];
        if (r == 0 && tid == 0) {
            float* o = new_xyz + ((size_t)b * Pn + it) * 3;
            o[0] = qx; o[1] = qy; o[2] = qz;
        }
    }

    // No CTA may exit while peers might still write into its mailbox.
    asm volatile("barrier.cluster.arrive.aligned;" ::: "memory");
    asm volatile("barrier.cluster.wait.aligned;"   ::: "memory");
}

// ---------------------------------------------------------------------------
// Kernel 2: Ball query — one warp per center, 8 centers (same batch) per block.
// First nsample in-ball indices in ascending order; pad with first hit (0 if
// none). Early exit once 64 found. Exact (non-contracted) distance + strict <.
// ---------------------------------------------------------------------------
__global__ __launch_bounds__(256)
void ballq_kernel(const float* __restrict__ xyz, const float* __restrict__ new_xyz)
{
    const int wglobal = blockIdx.x * 8 + (threadIdx.x >> 5);  // center id 0..4095
    const int b    = wglobal >> 10;
    const int lane = threadIdx.x & 31;

    const float* pts = xyz + (size_t)b * Nn * 3;
    const float* c   = new_xyz + (size_t)wglobal * 3;
    const float cx = c[0], cy = c[1], cz = c[2];
    int* oidx = g_ball_idx + (size_t)wglobal * Sn;

    const float R2 = (float)(0.3 * 0.3);   // same double->f32 path as JAX

    int  cnt   = 0;
    int  first = 0;
    bool have  = false;

    for (int base = 0; base < Nn; base += 32) {
        const int j = base + lane;
        float x = pts[j * 3 + 0];
        float y = pts[j * 3 + 1];
        float z = pts[j * 3 + 2];
        float dx = __fadd_rn(cx, -x);
        float dy = __fadd_rn(cy, -y);
        float dz = __fadd_rn(cz, -z);
        float d  = __fadd_rn(__fadd_rn(__fmul_rn(dx, dx), __fmul_rn(dy, dy)),
                             __fmul_rn(dz, dz));
        bool in = d < R2;
        unsigned m = __ballot_sync(0xffffffffu, in);
        if (m) {
            if (!have) { first = base + (__ffs(m) - 1); have = true; }
            if (in) {
                int pos = cnt + __popc(m & ((1u << lane) - 1u));
                if (pos < Sn) oidx[pos] = j;
            }
            cnt += __popc(m);
            if (cnt >= Sn) break;
        }
    }
    if (cnt < Sn) {
        for (int s = cnt + lane; s < Sn; s += 32) oidx[s] = first;  // 0 if none
    }
}

// ---------------------------------------------------------------------------
// Kernel 3: gather + MLP(6->64->64->128, relu) + max over samples.
// Block = 128 threads = 2 centers, thread = one sample.
// Weights in smem (W1,W3 transposed; W3 rows padded to 132 floats for
// conflict-free transpose + 16B-aligned float4 broadcast reads).
// Layers 2+3 fused: h2_i consumed immediately, h1[64]+h3[128] in registers.
// ---------------------------------------------------------------------------
constexpr int SW_FLOATS = 384 + 64 + 4096 + 64 + 64 * 132 + 128;  // 13184

__global__ __launch_bounds__(128)
void group_mlp_kernel(const float* __restrict__ xyz, const float* __restrict__ features,
                      const float* __restrict__ W1, const float* __restrict__ b1,
                      const float* __restrict__ W2, const float* __restrict__ b2,
                      const float* __restrict__ W3, const float* __restrict__ b3,
                      const float* __restrict__ new_xyz, float* __restrict__ out_feat)
{
    extern __shared__ float sw[];
    float* w1t = sw;                 // [6][64]   w1t[c*64+o] = W1[o][c]
    float* b1s = w1t + 384;          // [64]
    float* w2s = b1s + 64;           // [64][64]  row i = W2[i][:]
    float* b2s = w2s + 4096;         // [64]
    float* w3t = b2s + 64;           // [64][132] w3t[i*132+o] = W3[o][i]
    float* b3s = w3t + 64 * 132;     // [128]

    const int tid = threadIdx.x;

    for (int j = tid; j < 384; j += 128) {
        int cc = j >> 6, o = j & 63;
        w1t[j] = W1[o * 6 + cc];
    }
    if (tid < 64)  b1s[tid] = b1[tid];
    for (int j = tid; j < 4096; j += 128) w2s[j] = W2[j];
    if (tid < 64)  b2s[tid] = b2[tid];
    for (int j = tid; j < 8192; j += 128) {          // coalesced read, ~4-way STS
        int i = j & 63, o = j >> 6;
        w3t[i * 132 + o] = W3[j];
    }
    if (tid < 128) b3s[tid] = b3[tid];
    __syncthreads();

    const int cl = tid >> 6;                  // which of the 2 centers
    const int s  = tid & 63;                  // sample id
    const int center = blockIdx.x * 2 + cl;
    const int b  = center >> 10;
    const int gi = g_ball_idx[center * Sn + s];

    const float* pb = xyz      + (size_t)b * Nn * 3;
    const float* fb = features + (size_t)b * Nn * 3;
    const float* c  = new_xyz  + (size_t)center * 3;

    float g[6];
    g[0] = pb[gi * 3 + 0] - c[0];
    g[1] = pb[gi * 3 + 1] - c[1];
    g[2] = pb[gi * 3 + 2] - c[2];
    g[3] = fb[gi * 3 + 0];
    g[4] = fb[gi * 3 + 1];
    g[5] = fb[gi * 3 + 2];

    // ---- layer 1 ----
    float h1[64];
#pragma unroll
    for (int o = 0; o < 64; o += 4) {
        float4 bv = *reinterpret_cast<const float4*>(b1s + o);
        h1[o] = bv.x; h1[o + 1] = bv.y; h1[o + 2] = bv.z; h1[o + 3] = bv.w;
    }
#pragma unroll
    for (int cc = 0; cc < 6; ++cc) {
        float gv = g[cc];
        const float4* wr = reinterpret_cast<const float4*>(w1t + cc * 64);
#pragma unroll
        for (int o = 0; o < 64; o += 4) {
            float4 w = wr[o >> 2];
            h1[o]     += w.x * gv;
            h1[o + 1] += w.y * gv;
            h1[o + 2] += w.z * gv;
            h1[o + 3] += w.w * gv;
        }
    }
#pragma unroll
    for (int o = 0; o < 64; ++o) h1[o] = fmaxf(h1[o], 0.0f);

    // ---- fused layers 2+3 ----
    float h3[128];
#pragma unroll
    for (int o = 0; o < 128; o += 4) {
        float4 bv = *reinterpret_cast<const float4*>(b3s + o);
        h3[o] = bv.x; h3[o + 1] = bv.y; h3[o + 2] = bv.z; h3[o + 3] = bv.w;
    }

    for (int i = 0; i < 64; ++i) {
        const float4* w2r = reinterpret_cast<const float4*>(w2s + (i << 6));
        float a0 = 0.f, a1 = 0.f, a2 = 0.f, a3 = 0.f;
#pragma unroll
        for (int j = 0; j < 64; j += 16) {
            float4 wA = w2r[(j >> 2) + 0];
            float4 wB = w2r[(j >> 2) + 1];
            float4 wC = w2r[(j >> 2) + 2];
            float4 wD = w2r[(j >> 2) + 3];
            a0 += wA.x * h1[j + 0]  + wA.y * h1[j + 1]  + wA.z * h1[j + 2]  + wA.w * h1[j + 3];
            a1 += wB.x * h1[j + 4]  + wB.y * h1[j + 5]  + wB.z * h1[j + 6]  + wB.w * h1[j + 7];
            a2 += wC.x * h1[j + 8]  + wC.y * h1[j + 9]  + wC.z * h1[j + 10] + wC.w * h1[j + 11];
            a3 += wD.x * h1[j + 12] + wD.y * h1[j + 13] + wD.z * h1[j + 14] + wD.w * h1[j + 15];
        }
        float h2i = fmaxf(((a0 + a1) + (a2 + a3)) + b2s[i], 0.0f);

        const float4* w3r = reinterpret_cast<const float4*>(w3t + i * 132);
#pragma unroll
        for (int o = 0; o < 128; o += 4) {
            float4 w = w3r[o >> 2];
            h3[o]     += w.x * h2i;
            h3[o + 1] += w.y * h2i;
            h3[o + 2] += w.z * h2i;
            h3[o + 3] += w.w * h2i;
        }
    }

#pragma unroll
    for (int o = 0; o < 128; ++o) h3[o] = fmaxf(h3[o], 0.0f);

    // ---- max over 64 samples (2 warps per center) ----
#pragma unroll
    for (int o = 0; o < 128; ++o) {
#pragma unroll
        for (int off = 16; off > 0; off >>= 1)
            h3[o] = fmaxf(h3[o], __shfl_down_sync(0xffffffffu, h3[o], off));
    }
    __shared__ float red[4][128];
    const int wid = tid >> 5, lane = tid & 31;
    if (lane == 0) {
#pragma unroll
        for (int o = 0; o < 128; ++o) red[wid][o] = h3[o];
    }
    __syncthreads();
    for (int t = tid; t < 256; t += 128) {
        int cc = t >> 7, oo = t & 127;
        float v = fmaxf(red[2 * cc][oo], red[2 * cc + 1][oo]);
        int ctr = blockIdx.x * 2 + cc;
        int bb = ctr >> 10, pp = ctr & 1023;
        out_feat[(size_t)bb * (128 * Pn) + (size_t)oo * Pn + pp] = v;
    }
}

// ---------------------------------------------------------------------------
// Launch: fps (clustered) -> ball query -> group+MLP.
// Output = [new_xyz | new_features].
// ---------------------------------------------------------------------------
extern "C" void kernel_launch(void* const* d_in, const int* in_sizes, int n_in,
                              void* d_out, int out_size)
{
    (void)in_sizes; (void)n_in; (void)out_size;

    const float* xyz      = (const float*)d_in[0];
    const float* features = (const float*)d_in[1];
    const float* W1 = (const float*)d_in[2];
    const float* b1 = (const float*)d_in[3];
    const float* W2 = (const float*)d_in[4];
    const float* b2 = (const float*)d_in[5];
    const float* W3 = (const float*)d_in[6];
    const float* b3 = (const float*)d_in[7];

    float* out      = (float*)d_out;
    float* new_xyz  = out;                         // (B, P, 3)
    float* out_feat = out + (size_t)Bn * Pn * 3;   // (B, 128, P)

    const int mlp_smem = SW_FLOATS * (int)sizeof(float);      // 52736

    cudaFuncSetAttribute(fps_kernel,
                         cudaFuncAttributeMaxDynamicSharedMemorySize, FPS_SMEM);
    cudaFuncSetAttribute(group_mlp_kernel,
                         cudaFuncAttributeMaxDynamicSharedMemorySize, mlp_smem);

    fps_kernel<<<Bn * FPS_CL, FPS_NT, FPS_SMEM>>>(xyz, new_xyz);
    ballq_kernel<<<(Bn * Pn) / 8, 256>>>(xyz, new_xyz);
    group_mlp_kernel<<<(Bn * Pn) / 2, 128, mlp_smem>>>(
        xyz, features, W1, b1, W2, b2, W3, b3, new_xyz, out_feat);
}

// round 11
// speedup vs baseline: 1.8020x; 1.0173x over previous
#include <cuda_runtime.h>

// Problem constants (fixed shapes from the reference)
constexpr int Bn = 4;       // batch
constexpr int Nn = 16384;   // points per cloud
constexpr int Pn = 1024;    // npoint (FPS samples)
constexpr int Sn = 64;      // nsample (ball query)

// Scratch: ball query indices (B,P,S). 1 MB.
__device__ int g_ball_idx[Bn * Pn * Sn];

// ---- packed f32x2 helpers (sm_100+). Per-lane semantics identical to
// __fadd_rn / __fmul_rn / __fmaf_rn.
typedef unsigned long long ull;
__device__ __forceinline__ ull pk2(float lo, float hi) {
    ull r; asm("mov.b64 %0,{%1,%2};" : "=l"(r) : "f"(lo), "f"(hi)); return r;
}
__device__ __forceinline__ void upk2(ull v, float& lo, float& hi) {
    asm("mov.b64 {%0,%1},%2;" : "=f"(lo), "=f"(hi) : "l"(v));
}
__device__ __forceinline__ ull addx2(ull a, ull b) {
    ull r; asm("add.rn.f32x2 %0,%1,%2;" : "=l"(r) : "l"(a), "l"(b)); return r;
}
__device__ __forceinline__ ull mulx2(ull a, ull b) {
    ull r; asm("mul.rn.f32x2 %0,%1,%2;" : "=l"(r) : "l"(a), "l"(b)); return r;
}
__device__ __forceinline__ ull fmax2(ull a, ull b, ull c) {   // a*b+c
    ull r; asm("fma.rn.f32x2 %0,%1,%2,%3;" : "=l"(r) : "l"(a), "l"(b), "l"(c));
    return r;
}
__device__ __forceinline__ unsigned mapa_sh(unsigned addr, int rank) {
    unsigned r;
    asm("mapa.shared::cluster.u32 %0, %1, %2;" : "=r"(r) : "r"(addr), "r"(rank));
    return r;
}
__device__ __forceinline__ ull umax64(ull a, ull b) { return a > b ? a : b; }

// ---------------------------------------------------------------------------
// Kernel 1: Furthest Point Sampling — 8-CTA cluster per batch.
// Each CTA (256 threads) owns 2048 points fully in registers (packed f32x2);
// full-cloud coord copy in smem for the per-iter broadcast read.
// Per iteration (ONE __syncthreads, NO atomics, NO barrier.cluster):
//   redux.max (dist bits) + gated redux.min (global idx) per warp,
//   lane0 -> skey8[wid] (8 distinct slots), BAR,
//   warp0 lanes 0..7 EACH reduce the 8 keys (broadcast LDS, identical result),
//   stamp the iteration tag (bits 14..23) and store to destination CTA = lane
//   (one predicated st.shared::cluster, 8 parallel remote stores),
//   every thread polls its LOCAL mailbox (4x LDS.128) until all 8 slots carry
//   the tag, then max key => (max dist, then min global idx) == jnp.argmax.
// ---------------------------------------------------------------------------
constexpr int FPS_CL   = 8;                 // CTAs per batch (cluster size)
constexpr int FPS_PART = Nn / FPS_CL;       // 2048 points per CTA
constexpr int FPS_NT   = 256;               // threads per CTA
constexpr int FPS_PPT  = FPS_PART / FPS_NT; // 8 points per thread
constexpr int FPS_NPAIR = FPS_PPT / 2;      // 4 packed pairs per thread
// smem: float sxy[2*Nn] + szf[Nn], then ull skey8[8] + mbox[2][8]
constexpr int FPS_SMEM = 3 * Nn * 4 + 24 * 8;

__global__ __launch_bounds__(FPS_NT, 1) __cluster_dims__(FPS_CL, 1, 1)
void fps_kernel(const float* __restrict__ xyz, float* __restrict__ new_xyz)
{
    const int b = blockIdx.x / FPS_CL;
    const int r = blockIdx.x % FPS_CL;     // cluster rank
    const float* pts = xyz + (size_t)b * Nn * 3;

    extern __shared__ float sm[];
    float2* sxy   = reinterpret_cast<float2*>(sm);   // [Nn]
    float*  szf   = sm + 2 * Nn;                     // [Nn]
    ull*    skey8 = reinterpret_cast<ull*>(sm + 3 * Nn);  // [8]
    ull*    mbox  = skey8 + 8;                       // [2][8]

    const int tid  = threadIdx.x;
    const int lane = tid & 31;
    const int wid  = tid >> 5;

    // Stage the full cloud into this CTA's smem (for broadcasts).
    for (int p = tid; p < Nn; p += FPS_NT) {
        float x = pts[p * 3 + 0];
        float y = pts[p * 3 + 1];
        float z = pts[p * 3 + 2];
        sxy[p] = make_float2(x, y);
        szf[p] = z;
    }
    if (tid < 16) mbox[tid] = 0ull;        // tag 0 (never used: it >= 1)
    __syncthreads();
    // Mailbox init must be cluster-visible before any remote store (startup
    // only — no cluster barrier inside the loop).
    asm volatile("barrier.cluster.arrive.aligned;" ::: "memory");
    asm volatile("barrier.cluster.wait.aligned;"   ::: "memory");

    // Remote mailbox address: thread t<8 owns destination CTA t, slot r.
    const unsigned mbox_l  = (unsigned)__cvta_generic_to_shared(mbox);
    const unsigned rm_dest = (tid < FPS_CL)
        ? mapa_sh(mbox_l + (unsigned)(r * 8), tid) : 0u;

    // This CTA's 2048-point partition -> registers, packed pairs.
    // Slot m (0..7) <-> global index base + m*FPS_NT + tid; pair j packs
    // slots (j, j+NPAIR) so slot order == ascending global index per thread.
    const int base = r * FPS_PART;
    ull rx[FPS_NPAIR], ry[FPS_NPAIR], rz[FPS_NPAIR];
#pragma unroll
    for (int j = 0; j < FPS_NPAIR; ++j) {
        const int pA = base + j * FPS_NT + tid;
        const int pB = pA + FPS_NPAIR * FPS_NT;
        float2 a = sxy[pA], c = sxy[pB];
        rx[j] = pk2(a.x, c.x);
        ry[j] = pk2(a.y, c.y);
        rz[j] = pk2(szf[pA], szf[pB]);
    }
    float md[FPS_PPT];
#pragma unroll
    for (int k = 0; k < FPS_PPT; ++k) md[k] = 1e10f;   // matches jnp 1e10 init

    // First selected point is index 0.
    float qx = sxy[0].x, qy = sxy[0].y, qz = szf[0];
    if (r == 0 && tid == 0) {
        float* o = new_xyz + (size_t)b * Pn * 3;
        o[0] = qx; o[1] = qy; o[2] = qz;
    }

    for (int it = 1; it < Pn; ++it) {
        const ull nqx = pk2(-qx, -qx);
        const ull nqy = pk2(-qy, -qy);
        const ull nqz = pk2(-qz, -qz);

        float vm0 = -1.0f, vm1 = -1.0f;
#pragma unroll
        for (int j = 0; j < FPS_NPAIR; ++j) {
            ull dx = addx2(rx[j], nqx);            // == __fadd_rn(x, -qx)
            ull dy = addx2(ry[j], nqy);
            ull dz = addx2(rz[j], nqz);
            ull s  = addx2(addx2(mulx2(dx, dx), mulx2(dy, dy)), mulx2(dz, dz));
            float d0, d1; upk2(s, d0, d1);
            md[j]             = fminf(md[j],             d0);
            md[j + FPS_NPAIR] = fminf(md[j + FPS_NPAIR], d1);
            vm0 = fmaxf(vm0, md[j]);
            vm1 = fmaxf(vm1, md[j + FPS_NPAIR]);
        }
        const unsigned vb = __float_as_uint(fmaxf(vm0, vm1));

        // Warp max of distance bits (nonneg floats: bit order == float order),
        // then min global index among the warp's winners (first-match tiebreak).
        const unsigned wb = __reduce_max_sync(0xffffffffu, vb);
        unsigned loc = 0xffffffffu;
        if (vb == wb) {
            int bk = 0;
#pragma unroll
            for (int m = FPS_PPT - 1; m >= 0; --m)
                if (__float_as_uint(md[m]) == wb) bk = m;   // smallest slot
            loc = (unsigned)(base + bk * FPS_NT + tid);
        }
        const unsigned lmin = __reduce_min_sync(0xffffffffu, loc);  // <= 16383

        if (lane == 0)
            skey8[wid] = ((ull)wb << 32) | (unsigned)(0x3FFF - lmin);
        __syncthreads();

        const int buf = it & 1;
        const unsigned tag = (unsigned)(it & 0x3FF);
        if (tid < FPS_CL) {
            // All 8 lanes compute the identical block key (broadcast LDS),
            // then each stores to its own destination CTA — 8 parallel
            // remote stores from ONE predicated instruction.
            const ulonglong2* k2p = reinterpret_cast<const ulonglong2*>(skey8);
            ulonglong2 a0 = k2p[0], a1 = k2p[1], a2 = k2p[2], a3 = k2p[3];
            ull bk = umax64(umax64(umax64(a0.x, a0.y), umax64(a1.x, a1.y)),
                            umax64(umax64(a2.x, a2.y), umax64(a3.x, a3.y)));
            bk |= (ull)tag << 14;                  // idx bits 0..13, tag 14..23
            asm volatile("st.shared::cluster.u64 [%0], %1;"
                         :: "r"(rm_dest + (unsigned)(buf * FPS_CL * 8)),
                            "l"(bk) : "memory");
        }

        // Poll local mailbox (4x LDS.128) until all 8 slots carry this tag.
        const unsigned mba = mbox_l + (unsigned)(buf * FPS_CL * 8);
        ull k[8];
        for (;;) {
            asm volatile("ld.volatile.shared.v2.u64 {%0,%1},[%2];"
                         : "=l"(k[0]), "=l"(k[1]) : "r"(mba));
            asm volatile("ld.volatile.shared.v2.u64 {%0,%1},[%2];"
                         : "=l"(k[2]), "=l"(k[3]) : "r"(mba + 16));
            asm volatile("ld.volatile.shared.v2.u64 {%0,%1},[%2];"
                         : "=l"(k[4]), "=l"(k[5]) : "r"(mba + 32));
            asm volatile("ld.volatile.shared.v2.u64 {%0,%1},[%2];"
                         : "=l"(k[6]), "=l"(k[7]) : "r"(mba + 48));
            unsigned bad = 0;
#pragma unroll
            for (int q = 0; q < 8; ++q)
                bad |= ((unsigned)(k[q] >> 14) & 0x3FFu) ^ tag;
            if (!bad) break;
        }

        // Winner across CTAs: max packed key (max dist, then min index).
        ull kk = umax64(umax64(umax64(k[0], k[1]), umax64(k[2], k[3])),
                        umax64(umax64(k[4], k[5]), umax64(k[6], k[7])));
        const int sel = (int)(0x3FFFu - ((unsigned)kk & 0x3FFFu));

        float2 qv = sxy[sel];                      // local smem broadcast
        qx = qv.x; qy = qv.y; qz = szf[sel];
        if (r == 0 && tid == 0) {
            float* o = new_xyz + ((size_t)b * Pn + it) * 3;
            o[0] = qx; o[1] = qy; o[2] = qz;
        }
    }

    // No CTA may exit while peers might still write into its mailbox.
    asm volatile("barrier.cluster.arrive.aligned;" ::: "memory");
    asm volatile("barrier.cluster.wait.aligned;"   ::: "memory");
}

// ---------------------------------------------------------------------------
// Kernel 2: Ball query — one warp per center, 8 centers (same batch) per block.
// First nsample in-ball indices in ascending order; pad with first hit (0 if
// none). Early exit once 64 found. Exact (non-contracted) distance + strict <.
// ---------------------------------------------------------------------------
__global__ __launch_bounds__(256)
void ballq_kernel(const float* __restrict__ xyz, const float* __restrict__ new_xyz)
{
    const int wglobal = blockIdx.x * 8 + (threadIdx.x >> 5);  // center id 0..4095
    const int b    = wglobal >> 10;
    const int lane = threadIdx.x & 31;

    const float* pts = xyz + (size_t)b * Nn * 3;
    const float* c   = new_xyz + (size_t)wglobal * 3;
    const float cx = c[0], cy = c[1], cz = c[2];
    int* oidx = g_ball_idx + (size_t)wglobal * Sn;

    const float R2 = (float)(0.3 * 0.3);   // same double->f32 path as JAX

    int  cnt   = 0;
    int  first = 0;
    bool have  = false;

    for (int base = 0; base < Nn; base += 32) {
        const int j = base + lane;
        float x = pts[j * 3 + 0];
        float y = pts[j * 3 + 1];
        float z = pts[j * 3 + 2];
        float dx = __fadd_rn(cx, -x);
        float dy = __fadd_rn(cy, -y);
        float dz = __fadd_rn(cz, -z);
        float d  = __fadd_rn(__fadd_rn(__fmul_rn(dx, dx), __fmul_rn(dy, dy)),
                             __fmul_rn(dz, dz));
        bool in = d < R2;
        unsigned m = __ballot_sync(0xffffffffu, in);
        if (m) {
            if (!have) { first = base + (__ffs(m) - 1); have = true; }
            if (in) {
                int pos = cnt + __popc(m & ((1u << lane) - 1u));
                if (pos < Sn) oidx[pos] = j;
            }
            cnt += __popc(m);
            if (cnt >= Sn) break;
        }
    }
    if (cnt < Sn) {
        for (int s = cnt + lane; s < Sn; s += 32) oidx[s] = first;  // 0 if none
    }
}

// ---------------------------------------------------------------------------
// Kernel 3: gather + MLP(6->64->64->128, relu) + max over samples.
// Block = 128 threads = 2 centers, thread = one sample.
// All MLP math in packed f32x2 (FFMA2): h1 (32 ull), h3 (64 ull), L2 uses 4
// packed accumulator chains. fp32 precision throughout; only summation
// grouping differs from scalar (irrelevant at 1e-3 tolerance).
// Weights in smem (W1,W3 transposed; W3 rows padded to 132 floats).
// ---------------------------------------------------------------------------
constexpr int SW_FLOATS = 384 + 64 + 4096 + 64 + 64 * 132 + 128;  // 13184

__global__ __launch_bounds__(128)
void group_mlp_kernel(const float* __restrict__ xyz, const float* __restrict__ features,
                      const float* __restrict__ W1, const float* __restrict__ b1,
                      const float* __restrict__ W2, const float* __restrict__ b2,
                      const float* __restrict__ W3, const float* __restrict__ b3,
                      const float* __restrict__ new_xyz, float* __restrict__ out_feat)
{
    extern __shared__ float sw[];
    float* w1t = sw;                 // [6][64]   w1t[c*64+o] = W1[o][c]
    float* b1s = w1t + 384;          // [64]
    float* w2s = b1s + 64;           // [64][64]  row i = W2[i][:]
    float* b2s = w2s + 4096;         // [64]
    float* w3t = b2s + 64;           // [64][132] w3t[i*132+o] = W3[o][i]
    float* b3s = w3t + 64 * 132;     // [128]

    const int tid = threadIdx.x;

    for (int j = tid; j < 384; j += 128) {
        int cc = j >> 6, o = j & 63;
        w1t[j] = W1[o * 6 + cc];
    }
    if (tid < 64)  b1s[tid] = b1[tid];
    for (int j = tid; j < 4096; j += 128) w2s[j] = W2[j];
    if (tid < 64)  b2s[tid] = b2[tid];
    for (int j = tid; j < 8192; j += 128) {          // coalesced read, ~4-way STS
        int i = j & 63, o = j >> 6;
        w3t[i * 132 + o] = W3[j];
    }
    if (tid < 128) b3s[tid] = b3[tid];
    __syncthreads();

    const int cl = tid >> 6;                  // which of the 2 centers
    const int s  = tid & 63;                  // sample id
    const int center = blockIdx.x * 2 + cl;
    const int b  = center >> 10;
    const int gi = g_ball_idx[center * Sn + s];

    const float* pb = xyz      + (size_t)b * Nn * 3;
    const float* fb = features + (size_t)b * Nn * 3;
    const float* c  = new_xyz  + (size_t)center * 3;

    float g[6];
    g[0] = pb[gi * 3 + 0] - c[0];
    g[1] = pb[gi * 3 + 1] - c[1];
    g[2] = pb[gi * 3 + 2] - c[2];
    g[3] = fb[gi * 3 + 0];
    g[4] = fb[gi * 3 + 1];
    g[5] = fb[gi * 3 + 2];

    // ---- layer 1 (packed: 64 outputs in 32 ull regs) ----
    ull h1p[32];
    {
        const ull* b1u = reinterpret_cast<const ull*>(b1s);
#pragma unroll
        for (int k = 0; k < 32; ++k) h1p[k] = b1u[k];
    }
#pragma unroll
    for (int cc = 0; cc < 6; ++cc) {
        const ull gv = pk2(g[cc], g[cc]);
        const ull* wr = reinterpret_cast<const ull*>(w1t + cc * 64);
#pragma unroll
        for (int k = 0; k < 32; ++k) h1p[k] = fmax2(wr[k], gv, h1p[k]);
    }
#pragma unroll
    for (int k = 0; k < 32; ++k) {        // relu
        float lo, hi; upk2(h1p[k], lo, hi);
        h1p[k] = pk2(fmaxf(lo, 0.0f), fmaxf(hi, 0.0f));
    }

    // ---- fused layers 2+3 (packed) ----
    ull h3p[64];
    {
        const ull* b3u = reinterpret_cast<const ull*>(b3s);
#pragma unroll
        for (int k = 0; k < 64; ++k) h3p[k] = b3u[k];
    }

    for (int i = 0; i < 64; ++i) {
        const ulonglong2* w2r =
            reinterpret_cast<const ulonglong2*>(w2s + (i << 6));
        ull a0 = 0ull, a1 = 0ull, a2 = 0ull, a3 = 0ull;   // (0,0) packed
#pragma unroll
        for (int q = 0; q < 16; q += 2) {
            ulonglong2 w = w2r[q];
            ulonglong2 v = w2r[q + 1];
            a0 = fmax2(w.x, h1p[2 * q + 0], a0);
            a1 = fmax2(w.y, h1p[2 * q + 1], a1);
            a2 = fmax2(v.x, h1p[2 * q + 2], a2);
            a3 = fmax2(v.y, h1p[2 * q + 3], a3);
        }
        ull sp = addx2(addx2(a0, a1), addx2(a2, a3));
        float lo, hi; upk2(sp, lo, hi);
        const float h2i = fmaxf((lo + hi) + b2s[i], 0.0f);
        const ull h2p = pk2(h2i, h2i);

        const ulonglong2* w3r =
            reinterpret_cast<const ulonglong2*>(w3t + i * 132);
#pragma unroll
        for (int q = 0; q < 32; ++q) {
            ulonglong2 w = w3r[q];
            h3p[2 * q + 0] = fmax2(w.x, h2p, h3p[2 * q + 0]);
            h3p[2 * q + 1] = fmax2(w.y, h2p, h3p[2 * q + 1]);
        }
    }

    // ---- relu + max over 64 samples (2 warps per center) ----
    float h3[128];
#pragma unroll
    for (int k = 0; k < 64; ++k) {
        float lo, hi; upk2(h3p[k], lo, hi);
        h3[2 * k + 0] = fmaxf(lo, 0.0f);
        h3[2 * k + 1] = fmaxf(hi, 0.0f);
    }
#pragma unroll
    for (int o = 0; o < 128; ++o) {
#pragma unroll
        for (int off = 16; off > 0; off >>= 1)
            h3[o] = fmaxf(h3[o], __shfl_down_sync(0xffffffffu, h3[o], off));
    }
    __shared__ float red[4][128];
    const int wid = tid >> 5, lane = tid & 31;
    if (lane == 0) {
#pragma unroll
        for (int o = 0; o < 128; ++o) red[wid][o] = h3[o];
    }
    __syncthreads();
    for (int t = tid; t < 256; t += 128) {
        int cc = t >> 7, oo = t & 127;
        float v = fmaxf(red[2 * cc][oo], red[2 * cc + 1][oo]);
        int ctr = blockIdx.x * 2 + cc;
        int bb = ctr >> 10, pp = ctr & 1023;
        out_feat[(size_t)bb * (128 * Pn) + (size_t)oo * Pn + pp] = v;
    }
}

// ---------------------------------------------------------------------------
// Launch: fps (clustered) -> ball query -> group+MLP.
// Output = [new_xyz | new_features].
// ---------------------------------------------------------------------------
extern "C" void kernel_launch(void* const* d_in, const int* in_sizes, int n_in,
                              void* d_out, int out_size)
{
    (void)in_sizes; (void)n_in; (void)out_size;

    const float* xyz      = (const float*)d_in[0];
    const float* features = (const float*)d_in[1];
    const float* W1 = (const float*)d_in[2];
    const float* b1 = (const float*)d_in[3];
    const float* W2 = (const float*)d_in[4];
    const float* b2 = (const float*)d_in[5];
    const float* W3 = (const float*)d_in[6];
    const float* b3 = (const float*)d_in[7];

    float* out      = (float*)d_out;
    float* new_xyz  = out;                         // (B, P, 3)
    float* out_feat = out + (size_t)Bn * Pn * 3;   // (B, 128, P)

    const int mlp_smem = SW_FLOATS * (int)sizeof(float);      // 52736

    cudaFuncSetAttribute(fps_kernel,
                         cudaFuncAttributeMaxDynamicSharedMemorySize, FPS_SMEM);
    cudaFuncSetAttribute(group_mlp_kernel,
                         cudaFuncAttributeMaxDynamicSharedMemorySize, mlp_smem);

    fps_kernel<<<Bn * FPS_CL, FPS_NT, FPS_SMEM>>>(xyz, new_xyz);
    ballq_kernel<<<(Bn * Pn) / 8, 256>>>(xyz, new_xyz);
    group_mlp_kernel<<<(Bn * Pn) / 2, 128, mlp_smem>>>(
        xyz, features, W1, b1, W2, b2, W3, b3, new_xyz, out_feat);
}

// round 12
// speedup vs baseline: 1.8211x; 1.0106x over previous
#include <cuda_runtime.h>

// Problem constants (fixed shapes from the reference)
constexpr int Bn = 4;       // batch
constexpr int Nn = 16384;   // points per cloud
constexpr int Pn = 1024;    // npoint (FPS samples)
constexpr int Sn = 64;      // nsample (ball query)

// Scratch: ball query indices (B,P,S). 1 MB.
__device__ int g_ball_idx[Bn * Pn * Sn];

// ---- packed f32x2 helpers (sm_100+). Per-lane semantics identical to
// __fadd_rn / __fmul_rn / __fmaf_rn.
typedef unsigned long long ull;
__device__ __forceinline__ ull pk2(float lo, float hi) {
    ull r; asm("mov.b64 %0,{%1,%2};" : "=l"(r) : "f"(lo), "f"(hi)); return r;
}
__device__ __forceinline__ void upk2(ull v, float& lo, float& hi) {
    asm("mov.b64 {%0,%1},%2;" : "=f"(lo), "=f"(hi) : "l"(v));
}
__device__ __forceinline__ ull addx2(ull a, ull b) {
    ull r; asm("add.rn.f32x2 %0,%1,%2;" : "=l"(r) : "l"(a), "l"(b)); return r;
}
__device__ __forceinline__ ull mulx2(ull a, ull b) {
    ull r; asm("mul.rn.f32x2 %0,%1,%2;" : "=l"(r) : "l"(a), "l"(b)); return r;
}
__device__ __forceinline__ ull fmax2(ull a, ull b, ull c) {   // a*b+c
    ull r; asm("fma.rn.f32x2 %0,%1,%2,%3;" : "=l"(r) : "l"(a), "l"(b), "l"(c));
    return r;
}
__device__ __forceinline__ unsigned mapa_sh(unsigned addr, int rank) {
    unsigned r;
    asm("mapa.shared::cluster.u32 %0, %1, %2;" : "=r"(r) : "r"(addr), "r"(rank));
    return r;
}
__device__ __forceinline__ ull umax64(ull a, ull b) { return a > b ? a : b; }

// ---------------------------------------------------------------------------
// Kernel 1: Furthest Point Sampling — 8-CTA cluster per batch. (unchanged)
// ---------------------------------------------------------------------------
constexpr int FPS_CL   = 8;                 // CTAs per batch (cluster size)
constexpr int FPS_PART = Nn / FPS_CL;       // 2048 points per CTA
constexpr int FPS_NT   = 256;               // threads per CTA
constexpr int FPS_PPT  = FPS_PART / FPS_NT; // 8 points per thread
constexpr int FPS_NPAIR = FPS_PPT / 2;      // 4 packed pairs per thread
// smem: float sxy[2*Nn] + szf[Nn], then ull skey8[8] + mbox[2][8]
constexpr int FPS_SMEM = 3 * Nn * 4 + 24 * 8;

__global__ __launch_bounds__(FPS_NT, 1) __cluster_dims__(FPS_CL, 1, 1)
void fps_kernel(const float* __restrict__ xyz, float* __restrict__ new_xyz)
{
    const int b = blockIdx.x / FPS_CL;
    const int r = blockIdx.x % FPS_CL;     // cluster rank
    const float* pts = xyz + (size_t)b * Nn * 3;

    extern __shared__ float sm[];
    float2* sxy   = reinterpret_cast<float2*>(sm);   // [Nn]
    float*  szf   = sm + 2 * Nn;                     // [Nn]
    ull*    skey8 = reinterpret_cast<ull*>(sm + 3 * Nn);  // [8]
    ull*    mbox  = skey8 + 8;                       // [2][8]

    const int tid  = threadIdx.x;
    const int lane = tid & 31;
    const int wid  = tid >> 5;

    // Stage the full cloud into this CTA's smem (for broadcasts).
    for (int p = tid; p < Nn; p += FPS_NT) {
        float x = pts[p * 3 + 0];
        float y = pts[p * 3 + 1];
        float z = pts[p * 3 + 2];
        sxy[p] = make_float2(x, y);
        szf[p] = z;
    }
    if (tid < 16) mbox[tid] = 0ull;        // tag 0 (never used: it >= 1)
    __syncthreads();
    // Mailbox init must be cluster-visible before any remote store (startup
    // only — no cluster barrier inside the loop).
    asm volatile("barrier.cluster.arrive.aligned;" ::: "memory");
    asm volatile("barrier.cluster.wait.aligned;"   ::: "memory");

    // Remote mailbox address: thread t<8 owns destination CTA t, slot r.
    const unsigned mbox_l  = (unsigned)__cvta_generic_to_shared(mbox);
    const unsigned rm_dest = (tid < FPS_CL)
        ? mapa_sh(mbox_l + (unsigned)(r * 8), tid) : 0u;

    // This CTA's 2048-point partition -> registers, packed pairs.
    const int base = r * FPS_PART;
    ull rx[FPS_NPAIR], ry[FPS_NPAIR], rz[FPS_NPAIR];
#pragma unroll
    for (int j = 0; j < FPS_NPAIR; ++j) {
        const int pA = base + j * FPS_NT + tid;
        const int pB = pA + FPS_NPAIR * FPS_NT;
        float2 a = sxy[pA], c = sxy[pB];
        rx[j] = pk2(a.x, c.x);
        ry[j] = pk2(a.y, c.y);
        rz[j] = pk2(szf[pA], szf[pB]);
    }
    float md[FPS_PPT];
#pragma unroll
    for (int k = 0; k < FPS_PPT; ++k) md[k] = 1e10f;   // matches jnp 1e10 init

    // First selected point is index 0.
    float qx = sxy[0].x, qy = sxy[0].y, qz = szf[0];
    if (r == 0 && tid == 0) {
        float* o = new_xyz + (size_t)b * Pn * 3;
        o[0] = qx; o[1] = qy; o[2] = qz;
    }

    for (int it = 1; it < Pn; ++it) {
        const ull nqx = pk2(-qx, -qx);
        const ull nqy = pk2(-qy, -qy);
        const ull nqz = pk2(-qz, -qz);

        float vm0 = -1.0f, vm1 = -1.0f;
#pragma unroll
        for (int j = 0; j < FPS_NPAIR; ++j) {
            ull dx = addx2(rx[j], nqx);            // == __fadd_rn(x, -qx)
            ull dy = addx2(ry[j], nqy);
            ull dz = addx2(rz[j], nqz);
            ull s  = addx2(addx2(mulx2(dx, dx), mulx2(dy, dy)), mulx2(dz, dz));
            float d0, d1; upk2(s, d0, d1);
            md[j]             = fminf(md[j],             d0);
            md[j + FPS_NPAIR] = fminf(md[j + FPS_NPAIR], d1);
            vm0 = fmaxf(vm0, md[j]);
            vm1 = fmaxf(vm1, md[j + FPS_NPAIR]);
        }
        const unsigned vb = __float_as_uint(fmaxf(vm0, vm1));

        // Warp max of distance bits (nonneg floats: bit order == float order),
        // then min global index among the warp's winners (first-match tiebreak).
        const unsigned wb = __reduce_max_sync(0xffffffffu, vb);
        unsigned loc = 0xffffffffu;
        if (vb == wb) {
            int bk = 0;
#pragma unroll
            for (int m = FPS_PPT - 1; m >= 0; --m)
                if (__float_as_uint(md[m]) == wb) bk = m;   // smallest slot
            loc = (unsigned)(base + bk * FPS_NT + tid);
        }
        const unsigned lmin = __reduce_min_sync(0xffffffffu, loc);  // <= 16383

        if (lane == 0)
            skey8[wid] = ((ull)wb << 32) | (unsigned)(0x3FFF - lmin);
        __syncthreads();

        const int buf = it & 1;
        const unsigned tag = (unsigned)(it & 0x3FF);
        if (tid < FPS_CL) {
            const ulonglong2* k2p = reinterpret_cast<const ulonglong2*>(skey8);
            ulonglong2 a0 = k2p[0], a1 = k2p[1], a2 = k2p[2], a3 = k2p[3];
            ull bk = umax64(umax64(umax64(a0.x, a0.y), umax64(a1.x, a1.y)),
                            umax64(umax64(a2.x, a2.y), umax64(a3.x, a3.y)));
            bk |= (ull)tag << 14;                  // idx bits 0..13, tag 14..23
            asm volatile("st.shared::cluster.u64 [%0], %1;"
                         :: "r"(rm_dest + (unsigned)(buf * FPS_CL * 8)),
                            "l"(bk) : "memory");
        }

        // Poll local mailbox (4x LDS.128) until all 8 slots carry this tag.
        const unsigned mba = mbox_l + (unsigned)(buf * FPS_CL * 8);
        ull k[8];
        for (;;) {
            asm volatile("ld.volatile.shared.v2.u64 {%0,%1},[%2];"
                         : "=l"(k[0]), "=l"(k[1]) : "r"(mba));
            asm volatile("ld.volatile.shared.v2.u64 {%0,%1},[%2];"
                         : "=l"(k[2]), "=l"(k[3]) : "r"(mba + 16));
            asm volatile("ld.volatile.shared.v2.u64 {%0,%1},[%2];"
                         : "=l"(k[4]), "=l"(k[5]) : "r"(mba + 32));
            asm volatile("ld.volatile.shared.v2.u64 {%0,%1},[%2];"
                         : "=l"(k[6]), "=l"(k[7]) : "r"(mba + 48));
            unsigned bad = 0;
#pragma unroll
            for (int q = 0; q < 8; ++q)
                bad |= ((unsigned)(k[q] >> 14) & 0x3FFu) ^ tag;
            if (!bad) break;
        }

        // Winner across CTAs: max packed key (max dist, then min index).
        ull kk = umax64(umax64(umax64(k[0], k[1]), umax64(k[2], k[3])),
                        umax64(umax64(k[4], k[5]), umax64(k[6], k[7])));
        const int sel = (int)(0x3FFFu - ((unsigned)kk & 0x3FFFu));

        float2 qv = sxy[sel];                      // local smem broadcast
        qx = qv.x; qy = qv.y; qz = szf[sel];
        if (r == 0 && tid == 0) {
            float* o = new_xyz + ((size_t)b * Pn + it) * 3;
            o[0] = qx; o[1] = qy; o[2] = qz;
        }
    }

    // No CTA may exit while peers might still write into its mailbox.
    asm volatile("barrier.cluster.arrive.aligned;" ::: "memory");
    asm volatile("barrier.cluster.wait.aligned;"   ::: "memory");
}

// ---------------------------------------------------------------------------
// Kernel 2: Ball query — one warp per center, 8 centers (same batch) per block.
// (unchanged)
// ---------------------------------------------------------------------------
__global__ __launch_bounds__(256)
void ballq_kernel(const float* __restrict__ xyz, const float* __restrict__ new_xyz)
{
    const int wglobal = blockIdx.x * 8 + (threadIdx.x >> 5);  // center id 0..4095
    const int b    = wglobal >> 10;
    const int lane = threadIdx.x & 31;

    const float* pts = xyz + (size_t)b * Nn * 3;
    const float* c   = new_xyz + (size_t)wglobal * 3;
    const float cx = c[0], cy = c[1], cz = c[2];
    int* oidx = g_ball_idx + (size_t)wglobal * Sn;

    const float R2 = (float)(0.3 * 0.3);   // same double->f32 path as JAX

    int  cnt   = 0;
    int  first = 0;
    bool have  = false;

    for (int base = 0; base < Nn; base += 32) {
        const int j = base + lane;
        float x = pts[j * 3 + 0];
        float y = pts[j * 3 + 1];
        float z = pts[j * 3 + 2];
        float dx = __fadd_rn(cx, -x);
        float dy = __fadd_rn(cy, -y);
        float dz = __fadd_rn(cz, -z);
        float d  = __fadd_rn(__fadd_rn(__fmul_rn(dx, dx), __fmul_rn(dy, dy)),
                             __fmul_rn(dz, dz));
        bool in = d < R2;
        unsigned m = __ballot_sync(0xffffffffu, in);
        if (m) {
            if (!have) { first = base + (__ffs(m) - 1); have = true; }
            if (in) {
                int pos = cnt + __popc(m & ((1u << lane) - 1u));
                if (pos < Sn) oidx[pos] = j;
            }
            cnt += __popc(m);
            if (cnt >= Sn) break;
        }
    }
    if (cnt < Sn) {
        for (int s = cnt + lane; s < Sn; s += 32) oidx[s] = first;  // 0 if none
    }
}

// ---------------------------------------------------------------------------
// Kernel 3: gather + MLP(6->64->64->128, relu) + max over samples.
// Block = 128 threads = 2 centers, thread = one sample.
// Register-pressure-aware restructure:
//   L1 -> h1p[32] packed; L2 -> h2[64] scalar (h1p dies after);
//   L3 in TWO chunks of 64 outputs with accp[32] packed (h2+accp live).
// Peak live regs ~140 => no spills. All MACs are FFMA2 (fp32 precision).
// Sample-max uses __reduce_max_sync on relu'd bits (nonneg: uint order ==
// float order) — one REDUX per output instead of 5 SHFL+5 FMAX.
// ---------------------------------------------------------------------------
constexpr int SW_FLOATS = 384 + 64 + 4096 + 64 + 64 * 132 + 128;  // 13184

__global__ __launch_bounds__(128)
void group_mlp_kernel(const float* __restrict__ xyz, const float* __restrict__ features,
                      const float* __restrict__ W1, const float* __restrict__ b1,
                      const float* __restrict__ W2, const float* __restrict__ b2,
                      const float* __restrict__ W3, const float* __restrict__ b3,
                      const float* __restrict__ new_xyz, float* __restrict__ out_feat)
{
    extern __shared__ float sw[];
    float* w1t = sw;                 // [6][64]   w1t[c*64+o] = W1[o][c]
    float* b1s = w1t + 384;          // [64]
    float* w2s = b1s + 64;           // [64][64]  row i = W2[i][:]
    float* b2s = w2s + 4096;         // [64]
    float* w3t = b2s + 64;           // [64][132] w3t[i*132+o] = W3[o][i]
    float* b3s = w3t + 64 * 132;     // [128]

    const int tid = threadIdx.x;

    for (int j = tid; j < 384; j += 128) {
        int cc = j >> 6, o = j & 63;
        w1t[j] = W1[o * 6 + cc];
    }
    if (tid < 64)  b1s[tid] = b1[tid];
    for (int j = tid; j < 4096; j += 128) w2s[j] = W2[j];
    if (tid < 64)  b2s[tid] = b2[tid];
    for (int j = tid; j < 8192; j += 128) {          // coalesced read, ~4-way STS
        int i = j & 63, o = j >> 6;
        w3t[i * 132 + o] = W3[j];
    }
    if (tid < 128) b3s[tid] = b3[tid];
    __syncthreads();

    const int cl = tid >> 6;                  // which of the 2 centers
    const int s  = tid & 63;                  // sample id
    const int center = blockIdx.x * 2 + cl;
    const int b  = center >> 10;
    const int gi = g_ball_idx[center * Sn + s];

    const float* pb = xyz      + (size_t)b * Nn * 3;
    const float* fb = features + (size_t)b * Nn * 3;
    const float* c  = new_xyz  + (size_t)center * 3;

    float g[6];
    g[0] = pb[gi * 3 + 0] - c[0];
    g[1] = pb[gi * 3 + 1] - c[1];
    g[2] = pb[gi * 3 + 2] - c[2];
    g[3] = fb[gi * 3 + 0];
    g[4] = fb[gi * 3 + 1];
    g[5] = fb[gi * 3 + 2];

    // ---- layer 1 (packed: 64 outputs in 32 ull regs) ----
    ull h1p[32];
    {
        const ull* b1u = reinterpret_cast<const ull*>(b1s);
#pragma unroll
        for (int k = 0; k < 32; ++k) h1p[k] = b1u[k];
    }
#pragma unroll
    for (int cc = 0; cc < 6; ++cc) {
        const ull gv = pk2(g[cc], g[cc]);
        const ull* wr = reinterpret_cast<const ull*>(w1t + cc * 64);
#pragma unroll
        for (int k = 0; k < 32; ++k) h1p[k] = fmax2(wr[k], gv, h1p[k]);
    }
#pragma unroll
    for (int k = 0; k < 32; ++k) {        // relu
        float lo, hi; upk2(h1p[k], lo, hi);
        h1p[k] = pk2(fmaxf(lo, 0.0f), fmaxf(hi, 0.0f));
    }

    // ---- layer 2: materialize h2[64] (h1p dies after this loop) ----
    float h2[64];
#pragma unroll
    for (int i = 0; i < 64; ++i) {
        const ulonglong2* w2r =
            reinterpret_cast<const ulonglong2*>(w2s + (i << 6));
        ull a0 = 0ull, a1 = 0ull, a2 = 0ull, a3 = 0ull;   // (0,0) packed
#pragma unroll
        for (int q = 0; q < 16; q += 2) {
            ulonglong2 w = w2r[q];
            ulonglong2 v = w2r[q + 1];
            a0 = fmax2(w.x, h1p[2 * q + 0], a0);
            a1 = fmax2(w.y, h1p[2 * q + 1], a1);
            a2 = fmax2(v.x, h1p[2 * q + 2], a2);
            a3 = fmax2(v.y, h1p[2 * q + 3], a3);
        }
        ull sp = addx2(addx2(a0, a1), addx2(a2, a3));
        float lo, hi; upk2(sp, lo, hi);
        h2[i] = fmaxf((lo + hi) + b2s[i], 0.0f);
    }

    // ---- layer 3 in two chunks of 64 outputs + warp-level max (REDUX) ----
    __shared__ unsigned red[4][128];
    const int wid = tid >> 5, lane = tid & 31;

    for (int ch = 0; ch < 2; ++ch) {
        ull accp[32];
        {
            const ull* b3u = reinterpret_cast<const ull*>(b3s + ch * 64);
#pragma unroll
            for (int k = 0; k < 32; ++k) accp[k] = b3u[k];
        }
#pragma unroll
        for (int i = 0; i < 64; ++i) {
            const ull h2p = pk2(h2[i], h2[i]);
            const ulonglong2* w3r =
                reinterpret_cast<const ulonglong2*>(w3t + i * 132 + ch * 64);
#pragma unroll
            for (int q = 0; q < 16; ++q) {
                ulonglong2 w = w3r[q];
                accp[2 * q + 0] = fmax2(w.x, h2p, accp[2 * q + 0]);
                accp[2 * q + 1] = fmax2(w.y, h2p, accp[2 * q + 1]);
            }
        }
        // relu + per-warp max over 32 samples (one REDUX per output)
#pragma unroll
        for (int k = 0; k < 32; ++k) {
            float lo, hi; upk2(accp[k], lo, hi);
            unsigned mlo = __reduce_max_sync(
                0xffffffffu, __float_as_uint(fmaxf(lo, 0.0f)));
            unsigned mhi = __reduce_max_sync(
                0xffffffffu, __float_as_uint(fmaxf(hi, 0.0f)));
            if (lane == 0) {
                red[wid][ch * 64 + 2 * k + 0] = mlo;
                red[wid][ch * 64 + 2 * k + 1] = mhi;
            }
        }
    }
    __syncthreads();

    // Combine the two warps of each center; write (B,128,P) layout.
    for (int t = tid; t < 256; t += 128) {
        int cc = t >> 7, oo = t & 127;
        unsigned v = red[2 * cc][oo] > red[2 * cc + 1][oo]
                   ? red[2 * cc][oo] : red[2 * cc + 1][oo];
        int ctr = blockIdx.x * 2 + cc;
        int bb = ctr >> 10, pp = ctr & 1023;
        out_feat[(size_t)bb * (128 * Pn) + (size_t)oo * Pn + pp] =
            __uint_as_float(v);
    }
}

// ---------------------------------------------------------------------------
// Launch: fps (clustered) -> ball query -> group+MLP.
// Output = [new_xyz | new_features].
// ---------------------------------------------------------------------------
extern "C" void kernel_launch(void* const* d_in, const int* in_sizes, int n_in,
                              void* d_out, int out_size)
{
    (void)in_sizes; (void)n_in; (void)out_size;

    const float* xyz      = (const float*)d_in[0];
    const float* features = (const float*)d_in[1];
    const float* W1 = (const float*)d_in[2];
    const float* b1 = (const float*)d_in[3];
    const float* W2 = (const float*)d_in[4];
    const float* b2 = (const float*)d_in[5];
    const float* W3 = (const float*)d_in[6];
    const float* b3 = (const float*)d_in[7];

    float* out      = (float*)d_out;
    float* new_xyz  = out;                         // (B, P, 3)
    float* out_feat = out + (size_t)Bn * Pn * 3;   // (B, 128, P)

    const int mlp_smem = SW_FLOATS * (int)sizeof(float);      // 52736

    cudaFuncSetAttribute(fps_kernel,
                         cudaFuncAttributeMaxDynamicSharedMemorySize, FPS_SMEM);
    cudaFuncSetAttribute(group_mlp_kernel,
                         cudaFuncAttributeMaxDynamicSharedMemorySize, mlp_smem);

    fps_kernel<<<Bn * FPS_CL, FPS_NT, FPS_SMEM>>>(xyz, new_xyz);
    ballq_kernel<<<(Bn * Pn) / 8, 256>>>(xyz, new_xyz);
    group_mlp_kernel<<<(Bn * Pn) / 2, 128, mlp_smem>>>(
        xyz, features, W1, b1, W2, b2, W3, b3, new_xyz, out_feat);
}